// round 6
// baseline (speedup 1.0000x reference)
#include <cuda_runtime.h>
#include <math.h>
#include <stdint.h>

// Problem constants
#define B_ 2
#define T_ 2048
#define C_ 768
#define H_ 12
#define HD_ 64
#define BT_ (B_ * T_)   // 4096

// ---------------------------------------------------------------------------
// Scratch (device globals; no allocation allowed)
// ---------------------------------------------------------------------------
__device__ float g_ln[BT_ * C_];          // LN output (tf32-rounded)
__device__ float g_qkv[BT_ * 3 * C_];     // QKV (tf32-rounded)
__device__ float g_vt[B_ * H_ * HD_ * T_]; // V transposed [b][h][d][t]
__device__ float g_y[BT_ * C_];           // attention output (tf32-rounded)
__device__ float g_x1[BT_ * C_];          // x + attn (fp32)
__device__ float g_h[BT_ * 4 * C_];       // gelu(fc) (tf32-rounded)

// ---------------------------------------------------------------------------
// Helpers
// ---------------------------------------------------------------------------
__device__ __forceinline__ float to_tf32(float x) {
    uint32_t u;
    asm("cvt.rna.tf32.f32 %0, %1;" : "=r"(u) : "f"(x));
    return __uint_as_float(u);
}

__device__ __forceinline__ uint32_t smem_u32(const void* p) {
    uint32_t a;
    asm("{ .reg .u64 t; cvta.to.shared.u64 t, %1; cvt.u32.u64 %0, t; }"
        : "=r"(a) : "l"(p));
    return a;
}

#define CP_ASYNC16(dst, src) \
    asm volatile("cp.async.cg.shared.global [%0], [%1], 16;" :: "r"(dst), "l"(src))
#define CP_COMMIT() asm volatile("cp.async.commit_group;" ::: "memory")
#define CP_WAIT(n)  asm volatile("cp.async.wait_group %0;" :: "n"(n) : "memory")

__device__ __forceinline__ void mma_tf32(float* d, const float* a, const float* b) {
    asm volatile(
        "mma.sync.aligned.m16n8k8.row.col.f32.tf32.tf32.f32 "
        "{%0,%1,%2,%3}, {%4,%5,%6,%7}, {%8,%9}, {%0,%1,%2,%3};"
        : "+f"(d[0]), "+f"(d[1]), "+f"(d[2]), "+f"(d[3])
        : "r"(__float_as_uint(a[0])), "r"(__float_as_uint(a[1])),
          "r"(__float_as_uint(a[2])), "r"(__float_as_uint(a[3])),
          "r"(__float_as_uint(b[0])), "r"(__float_as_uint(b[1])));
}

// swizzled smem indices
#define SWIDX(m, k) ((m) * 32 + ((k) ^ (((m) & 7) << 2)))   // A tiles: [128 rows][32 k]
#define SW64(m, k)  ((m) * 64 + ((k) ^ (((m) & 7) << 2)))   // attn tiles: 64-float rows
#define BIDX(k, n)  ((k) * 128 + ((n) ^ (((k) & 3) << 3)))  // B tiles: [32 k][128 n]

// ---------------------------------------------------------------------------
// V transpose: g_vt[b][h][d][t] = qkv_v[b][t][h][d].
// grid(T/32, B*H*2), block(32,8)
// ---------------------------------------------------------------------------
__global__ void vt_kernel(const float* __restrict__ qkv, float* __restrict__ vt) {
    __shared__ float tile[32][33];
    int t0 = blockIdx.x * 32;
    int by = blockIdx.y;
    int bh = by >> 1, dt = by & 1;
    int d0 = dt * 32;
    int b = bh / H_, h = bh % H_;
    const float* src = qkv + (size_t)b * T_ * 3 * C_ + 2 * C_ + h * HD_;
#pragma unroll
    for (int i = threadIdx.y; i < 32; i += 8)
        tile[i][threadIdx.x] = src[(size_t)(t0 + i) * 3 * C_ + d0 + threadIdx.x];
    __syncthreads();
    float* dst = vt + (size_t)bh * HD_ * T_;
#pragma unroll
    for (int i = threadIdx.y; i < 32; i += 8)
        dst[(size_t)(d0 + i) * T_ + t0 + threadIdx.x] = tile[threadIdx.x][i];
}

// ---------------------------------------------------------------------------
// LayerNorm: one block (256 thr) per row of 768.  Output tf32-rounded.
// ---------------------------------------------------------------------------
__global__ void ln_kernel(const float* __restrict__ x, const float* __restrict__ g,
                          const float* __restrict__ b, float* __restrict__ out) {
    int row = blockIdx.x;
    const float* xr = x + (size_t)row * C_;
    float v[3];
    float s = 0.f, sq = 0.f;
#pragma unroll
    for (int i = 0; i < 3; i++) {
        v[i] = xr[threadIdx.x + i * 256];
        s += v[i];
        sq += v[i] * v[i];
    }
#pragma unroll
    for (int off = 16; off; off >>= 1) {
        s  += __shfl_xor_sync(0xffffffffu, s, off);
        sq += __shfl_xor_sync(0xffffffffu, sq, off);
    }
    __shared__ float ss[8], ssq[8];
    int w = threadIdx.x >> 5, lane = threadIdx.x & 31;
    if (lane == 0) { ss[w] = s; ssq[w] = sq; }
    __syncthreads();
    if (w == 0) {
        s = ss[lane & 7];
        sq = ssq[lane & 7];
#pragma unroll
        for (int off = 4; off; off >>= 1) {
            s  += __shfl_xor_sync(0xffffffffu, s, off);
            sq += __shfl_xor_sync(0xffffffffu, sq, off);
        }
        if (lane == 0) { ss[0] = s; ssq[0] = sq; }
    }
    __syncthreads();
    float mean = ss[0] * (1.0f / C_);
    float var  = ssq[0] * (1.0f / C_) - mean * mean;
    float rstd = rsqrtf(var + 1e-5f);
    float* outr = out + (size_t)row * C_;
#pragma unroll
    for (int i = 0; i < 3; i++) {
        int c = threadIdx.x + i * 256;
        outr[c] = to_tf32((v[i] - mean) * rstd * g[c] + b[c]);
    }
}

// ---------------------------------------------------------------------------
// mma.sync tf32 GEMM: C[M,N] = A[M,K] @ W[K,N]  (W used directly, no transpose)
// BM=BN=128, BK=32, 3-stage cp.async pipeline, 256 threads, occupancy 2.
// EPI: 0 none, 1 += res, 2 GELU+tf32, 3 tf32 round
// ---------------------------------------------------------------------------
#define STAGE_FLOATS 4096   // per operand per stage (128*32 or 32*128)
#define GEMM_SMEM (3 * 2 * STAGE_FLOATS * 4)   // 96KB

__device__ __forceinline__ void load_stage(uint32_t sa, uint32_t sb,
                                           const float* __restrict__ Ab,
                                           const float* __restrict__ Wb,
                                           int K, int N, int kb, int tid) {
    int k0 = kb * 32;
#pragma unroll
    for (int t = 0; t < 4; t++) {
        int linear = tid + t * 256;
        // A: 128 rows x 8 chunks of 4k
        int m = linear >> 3, ch = linear & 7;
        uint32_t swa = (uint32_t)((m * 32 + ((ch * 4) ^ ((m & 7) << 2))) * 4);
        CP_ASYNC16(sa + swa, Ab + (size_t)m * K + k0 + ch * 4);
        // B: 32 k-rows x 32 chunks of 4n
        int k = linear >> 5, c = linear & 31;
        uint32_t swb = (uint32_t)((k * 128 + ((c * 4) ^ ((k & 3) << 3))) * 4);
        CP_ASYNC16(sb + swb, Wb + (size_t)(k0 + k) * N + c * 4);
    }
}

template <int EPI>
__global__ __launch_bounds__(256, 2)
void tc_gemm(const float* __restrict__ A, const float* __restrict__ W,
             const float* __restrict__ res, float* __restrict__ Cm,
             int M, int N, int K) {
    extern __shared__ __align__(16) float dsm[];
    // layout: [3 stages][A 4096 | B 4096]
    uint32_t sbase = smem_u32(dsm);

    int tid = threadIdx.x;
    int wid = tid >> 5, lane = tid & 31;
    int warp_m = wid >> 2, warp_n = wid & 3;
    int lr = lane >> 2, lc = lane & 3;
    const int KB = K >> 5;

    const float* Ab = A + (size_t)blockIdx.y * 128 * K;
    const float* Wb = W + blockIdx.x * 128;

    float acc[4][4][4];
#pragma unroll
    for (int i = 0; i < 4; i++)
#pragma unroll
        for (int j = 0; j < 4; j++)
#pragma unroll
            for (int r = 0; r < 4; r++) acc[i][j][r] = 0.f;

    load_stage(sbase, sbase + STAGE_FLOATS * 4, Ab, Wb, K, N, 0, tid);
    CP_COMMIT();
    load_stage(sbase + 2 * STAGE_FLOATS * 4, sbase + 3 * STAGE_FLOATS * 4,
               Ab, Wb, K, N, 1, tid);
    CP_COMMIT();

    for (int kb = 0; kb < KB; kb++) {
        int s = kb % 3;
        if (kb + 1 < KB) { CP_WAIT(1); } else { CP_WAIT(0); }
        __syncthreads();
        if (kb + 2 < KB) {
            int sn = (kb + 2) % 3;
            load_stage(sbase + (2 * sn) * STAGE_FLOATS * 4,
                       sbase + (2 * sn + 1) * STAGE_FLOATS * 4,
                       Ab, Wb, K, N, kb + 2, tid);
            CP_COMMIT();
        }

        const float* as = dsm + (2 * s) * STAGE_FLOATS;
        const float* bs = dsm + (2 * s + 1) * STAGE_FLOATS;
#pragma unroll
        for (int ks = 0; ks < 4; ks++) {
            int k0 = ks * 8;
            float afr[4][4], bfr[4][2];
#pragma unroll
            for (int mt = 0; mt < 4; mt++) {
                int r0 = warp_m * 64 + mt * 16 + lr;
                afr[mt][0] = as[SWIDX(r0,     k0 + lc)];
                afr[mt][1] = as[SWIDX(r0 + 8, k0 + lc)];
                afr[mt][2] = as[SWIDX(r0,     k0 + lc + 4)];
                afr[mt][3] = as[SWIDX(r0 + 8, k0 + lc + 4)];
            }
#pragma unroll
            for (int nt = 0; nt < 4; nt++) {
                int n0 = warp_n * 32 + nt * 8 + lr;
                int sw = n0 ^ (lc << 3);
                bfr[nt][0] = bs[(k0 + lc) * 128 + sw];
                bfr[nt][1] = bs[(k0 + lc + 4) * 128 + sw];
            }
#pragma unroll
            for (int mt = 0; mt < 4; mt++)
#pragma unroll
                for (int nt = 0; nt < 4; nt++)
                    mma_tf32(acc[mt][nt], afr[mt], bfr[nt]);
        }
    }

    __syncthreads();   // all compute done before anything else; also orders exit
    int gm0 = blockIdx.y * 128 + warp_m * 64;
    int gn0 = blockIdx.x * 128 + warp_n * 32;
#pragma unroll
    for (int mt = 0; mt < 4; mt++) {
#pragma unroll
        for (int nt = 0; nt < 4; nt++) {
            int gm = gm0 + mt * 16 + lr;
            int gn = gn0 + nt * 8 + lc * 2;
#pragma unroll
            for (int half = 0; half < 2; half++) {
                int row = gm + half * 8;
                size_t off = (size_t)row * N + gn;
                float2 v;
                v.x = acc[mt][nt][half * 2 + 0];
                v.y = acc[mt][nt][half * 2 + 1];
                if (EPI == 1) {
                    float2 rs = *(const float2*)(res + off);
                    v.x += rs.x; v.y += rs.y;
                }
                if (EPI == 2) {
                    v.x = to_tf32(0.5f * v.x * (1.0f + erff(v.x * 0.7071067811865475f)));
                    v.y = to_tf32(0.5f * v.y * (1.0f + erff(v.y * 0.7071067811865475f)));
                }
                if (EPI == 3) {
                    v.x = to_tf32(v.x);
                    v.y = to_tf32(v.y);
                }
                *(float2*)(Cm + off) = v;
            }
        }
    }
}

// ---------------------------------------------------------------------------
// Tensor-core flash attention (tf32, causal). Grid: (T/64, B*H). 128 threads.
// smem floats: Qs/Ps [0,4096) | Ks[2] [4096,12288) | Vt[2] [12288,20480)
// ---------------------------------------------------------------------------
#define ATTN_SMEM (20480 * 4)

__device__ __forceinline__ void attn_load_kv(uint32_t sb, const float* __restrict__ kbase,
                                             const float* __restrict__ vtb,
                                             int j, int s, int tid) {
    uint32_t kdst = sb + (uint32_t)(4096 + s * 4096) * 4;
    uint32_t vdst = sb + (uint32_t)(12288 + s * 4096) * 4;
#pragma unroll
    for (int t = 0; t < 8; t++) {
        int linear = tid + t * 128;
        int r = linear >> 4, ch = linear & 15;
        uint32_t sw = (uint32_t)((r * 64 + ((ch * 4) ^ ((r & 7) << 2))) * 4);
        CP_ASYNC16(kdst + sw, kbase + (size_t)(j * 64 + r) * 3 * C_ + ch * 4);
        CP_ASYNC16(vdst + sw, vtb + (size_t)r * T_ + j * 64 + ch * 4);
    }
}

__global__ __launch_bounds__(128)
void attn_tc(const float* __restrict__ qkv, const float* __restrict__ vt,
             float* __restrict__ y) {
    extern __shared__ __align__(16) float smf[];
    uint32_t sb = smem_u32(smf);

    int qb = blockIdx.x, bh = blockIdx.y;
    int b = bh / H_, h = bh % H_;
    int tid = threadIdx.x, wid = tid >> 5, lane = tid & 31;
    int lr = lane >> 2, lc = lane & 3;

    const float* qbase = qkv + (size_t)b * T_ * 3 * C_ + h * HD_;
    const float* kbase = qbase + C_;
    const float* vtb = vt + (size_t)bh * HD_ * T_;

#pragma unroll
    for (int t = 0; t < 8; t++) {
        int linear = tid + t * 128;
        int r = linear >> 4, ch = linear & 15;
        uint32_t sw = (uint32_t)((r * 64 + ((ch * 4) ^ ((r & 7) << 2))) * 4);
        CP_ASYNC16(sb + sw, qbase + (size_t)(qb * 64 + r) * 3 * C_ + ch * 4);
    }
    CP_COMMIT();
    attn_load_kv(sb, kbase, vtb, 0, 0, tid);
    CP_COMMIT();

    CP_WAIT(1);
    __syncthreads();

    int r0 = wid * 16 + lr;
    float qfr[8][4];
#pragma unroll
    for (int ks = 0; ks < 8; ks++) {
        qfr[ks][0] = smf[SW64(r0,     ks * 8 + lc)];
        qfr[ks][1] = smf[SW64(r0 + 8, ks * 8 + lc)];
        qfr[ks][2] = smf[SW64(r0,     ks * 8 + lc + 4)];
        qfr[ks][3] = smf[SW64(r0 + 8, ks * 8 + lc + 4)];
    }

    float oacc[8][4];
#pragma unroll
    for (int i = 0; i < 8; i++)
#pragma unroll
        for (int e = 0; e < 4; e++) oacc[i][e] = 0.f;
    float m0 = -1e30f, m1 = -1e30f, l0 = 0.f, l1 = 0.f;

    int rg0 = qb * 64 + r0;

    for (int j = 0; j <= qb; j++) {
        int s = j & 1;
        if (j < qb) {
            attn_load_kv(sb, kbase, vtb, j + 1, s ^ 1, tid);
            CP_COMMIT();
            CP_WAIT(1);
        } else {
            CP_WAIT(0);
        }
        __syncthreads();

        const float* ksm = smf + 4096 + s * 4096;
        const float* vsm = smf + 12288 + s * 4096;

        float sacc[8][4];
#pragma unroll
        for (int nf = 0; nf < 8; nf++)
#pragma unroll
            for (int e = 0; e < 4; e++) sacc[nf][e] = 0.f;
#pragma unroll
        for (int nf = 0; nf < 8; nf++) {
            int n0 = nf * 8 + lr;
#pragma unroll
            for (int ks = 0; ks < 8; ks++) {
                float bfr[2];
                bfr[0] = ksm[SW64(n0, ks * 8 + lc)];
                bfr[1] = ksm[SW64(n0, ks * 8 + lc + 4)];
                mma_tf32(sacc[nf], qfr[ks], bfr);
            }
        }

#pragma unroll
        for (int nf = 0; nf < 8; nf++) {
#pragma unroll
            for (int e = 0; e < 4; e++) {
                float v = sacc[nf][e] * 0.125f;
                if (j == qb) {
                    int col = j * 64 + nf * 8 + 2 * lc + (e & 1);
                    int row = (e < 2) ? rg0 : rg0 + 8;
                    if (col > row) v = -1e30f;
                }
                sacc[nf][e] = v;
            }
        }

        float ml0 = -1e30f, ml1 = -1e30f;
#pragma unroll
        for (int nf = 0; nf < 8; nf++) {
            ml0 = fmaxf(ml0, fmaxf(sacc[nf][0], sacc[nf][1]));
            ml1 = fmaxf(ml1, fmaxf(sacc[nf][2], sacc[nf][3]));
        }
#pragma unroll
        for (int off = 1; off < 4; off <<= 1) {
            ml0 = fmaxf(ml0, __shfl_xor_sync(0xffffffffu, ml0, off));
            ml1 = fmaxf(ml1, __shfl_xor_sync(0xffffffffu, ml1, off));
        }
        float mn0 = fmaxf(m0, ml0), mn1 = fmaxf(m1, ml1);
        float c0 = __expf(m0 - mn0), c1 = __expf(m1 - mn1);
        float ls0 = 0.f, ls1 = 0.f;
#pragma unroll
        for (int nf = 0; nf < 8; nf++) {
            int colb = nf * 8 + 2 * lc;
            float p0 = __expf(sacc[nf][0] - mn0);
            float p1 = __expf(sacc[nf][1] - mn0);
            float p2 = __expf(sacc[nf][2] - mn1);
            float p3 = __expf(sacc[nf][3] - mn1);
            ls0 += p0 + p1;
            ls1 += p2 + p3;
            smf[SW64(r0,     colb)]     = p0;
            smf[SW64(r0,     colb + 1)] = p1;
            smf[SW64(r0 + 8, colb)]     = p2;
            smf[SW64(r0 + 8, colb + 1)] = p3;
        }
#pragma unroll
        for (int off = 1; off < 4; off <<= 1) {
            ls0 += __shfl_xor_sync(0xffffffffu, ls0, off);
            ls1 += __shfl_xor_sync(0xffffffffu, ls1, off);
        }
        l0 = l0 * c0 + ls0;
        l1 = l1 * c1 + ls1;
        m0 = mn0; m1 = mn1;
#pragma unroll
        for (int nf = 0; nf < 8; nf++) {
            oacc[nf][0] *= c0;
            oacc[nf][1] *= c0;
            oacc[nf][2] *= c1;
            oacc[nf][3] *= c1;
        }
        __syncwarp();

#pragma unroll
        for (int ks = 0; ks < 8; ks++) {
            float pafr[4];
            pafr[0] = to_tf32(smf[SW64(r0,     ks * 8 + lc)]);
            pafr[1] = to_tf32(smf[SW64(r0 + 8, ks * 8 + lc)]);
            pafr[2] = to_tf32(smf[SW64(r0,     ks * 8 + lc + 4)]);
            pafr[3] = to_tf32(smf[SW64(r0 + 8, ks * 8 + lc + 4)]);
#pragma unroll
            for (int nf = 0; nf < 8; nf++) {
                float bfr[2];
                bfr[0] = vsm[SW64(nf * 8 + lr, ks * 8 + lc)];
                bfr[1] = vsm[SW64(nf * 8 + lr, ks * 8 + lc + 4)];
                mma_tf32(oacc[nf], pafr, bfr);
            }
        }
        __syncthreads();
    }

    float inv0 = 1.0f / l0, inv1 = 1.0f / l1;
#pragma unroll
    for (int nf = 0; nf < 8; nf++) {
        int gc = h * HD_ + nf * 8 + 2 * lc;
        size_t o0 = (size_t)(b * T_ + rg0) * C_ + gc;
        size_t o1 = (size_t)(b * T_ + rg0 + 8) * C_ + gc;
        float2 v0, v1;
        v0.x = to_tf32(oacc[nf][0] * inv0);
        v0.y = to_tf32(oacc[nf][1] * inv0);
        v1.x = to_tf32(oacc[nf][2] * inv1);
        v1.y = to_tf32(oacc[nf][3] * inv1);
        *(float2*)(y + o0) = v0;
        *(float2*)(y + o1) = v1;
    }
}

// ---------------------------------------------------------------------------
// Launch
// ---------------------------------------------------------------------------
extern "C" void kernel_launch(void* const* d_in, const int* in_sizes, int n_in,
                              void* d_out, int out_size) {
    const float* x       = (const float*)d_in[0];
    const float* ln1_g   = (const float*)d_in[1];
    const float* ln1_b   = (const float*)d_in[2];
    const float* W_qkv   = (const float*)d_in[3];
    const float* W_attn  = (const float*)d_in[4];
    const float* ln2_g   = (const float*)d_in[5];
    const float* ln2_b   = (const float*)d_in[6];
    const float* W_fc    = (const float*)d_in[7];
    const float* W_mlp   = (const float*)d_in[8];
    float* out = (float*)d_out;

    float *ln, *qkv, *vtb, *yb, *x1, *hb;
    cudaGetSymbolAddress((void**)&ln, g_ln);
    cudaGetSymbolAddress((void**)&qkv, g_qkv);
    cudaGetSymbolAddress((void**)&vtb, g_vt);
    cudaGetSymbolAddress((void**)&yb, g_y);
    cudaGetSymbolAddress((void**)&x1, g_x1);
    cudaGetSymbolAddress((void**)&hb, g_h);

    cudaFuncSetAttribute(tc_gemm<1>, cudaFuncAttributeMaxDynamicSharedMemorySize, GEMM_SMEM);
    cudaFuncSetAttribute(tc_gemm<2>, cudaFuncAttributeMaxDynamicSharedMemorySize, GEMM_SMEM);
    cudaFuncSetAttribute(tc_gemm<3>, cudaFuncAttributeMaxDynamicSharedMemorySize, GEMM_SMEM);
    cudaFuncSetAttribute(attn_tc, cudaFuncAttributeMaxDynamicSharedMemorySize, ATTN_SMEM);

    // 1) LN1
    ln_kernel<<<BT_, 256>>>(x, ln1_g, ln1_b, ln);
    // 2) QKV = ln1 @ W_qkv (tf32-rounded output)
    tc_gemm<3><<<dim3(3 * C_ / 128, BT_ / 128), 256, GEMM_SMEM>>>(ln, W_qkv, nullptr, qkv,
                                                                  BT_, 3 * C_, C_);
    // 3) V transpose
    vt_kernel<<<dim3(T_ / 32, B_ * H_ * 2), dim3(32, 8)>>>(qkv, vtb);
    // 4) tensor-core causal flash attention
    attn_tc<<<dim3(T_ / 64, B_ * H_), 128, ATTN_SMEM>>>(qkv, vtb, yb);
    // 5) x1 = x + y @ W_attn_proj
    tc_gemm<1><<<dim3(C_ / 128, BT_ / 128), 256, GEMM_SMEM>>>(yb, W_attn, x, x1,
                                                              BT_, C_, C_);
    // 6) LN2
    ln_kernel<<<BT_, 256>>>(x1, ln2_g, ln2_b, ln);
    // 7) h = gelu(ln2 @ W_fc)
    tc_gemm<2><<<dim3(4 * C_ / 128, BT_ / 128), 256, GEMM_SMEM>>>(ln, W_fc, nullptr, hb,
                                                                  BT_, 4 * C_, C_);
    // 8) out = x1 + h @ W_mlp_proj
    tc_gemm<1><<<dim3(C_ / 128, BT_ / 128), 256, GEMM_SMEM>>>(hb, W_mlp, x1, out,
                                                              BT_, C_, 4 * C_);
}

// round 11
// speedup vs baseline: 1.6800x; 1.6800x over previous
#include <cuda_runtime.h>
#include <cuda_fp16.h>
#include <math.h>
#include <stdint.h>

// Problem constants
#define B_ 2
#define T_ 2048
#define C_ 768
#define H_ 12
#define HD_ 64
#define BT_ (B_ * T_)   // 4096

// ---------------------------------------------------------------------------
// Scratch (device globals; no allocation allowed)
// ---------------------------------------------------------------------------
__device__ __half g_ln[BT_ * C_];            // LN output (fp16)
__device__ __half g_qkv[BT_ * 3 * C_];       // QKV (fp16)
__device__ __half g_vt[B_ * H_ * HD_ * T_];  // V transposed [b][h][d][t] fp16
__device__ __half g_y[BT_ * C_];             // attention output (fp16)
__device__ float  g_x1[BT_ * C_];            // x + attn (fp32)
__device__ __half g_h[BT_ * 4 * C_];         // gelu(fc) (fp16)
// fp16 transposed weights [N,K]
__device__ __half g_wq[3 * C_ * C_];
__device__ __half g_wa[C_ * C_];
__device__ __half g_wf[4 * C_ * C_];
__device__ __half g_wm[C_ * 4 * C_];

// ---------------------------------------------------------------------------
// Helpers
// ---------------------------------------------------------------------------
__device__ __forceinline__ uint32_t smem_u32(const void* p) {
    uint32_t a;
    asm("{ .reg .u64 t; cvta.to.shared.u64 t, %1; cvt.u32.u64 %0, t; }"
        : "=r"(a) : "l"(p));
    return a;
}

__device__ __forceinline__ uint32_t h2_as_u32(__half2 h) {
    union { __half2 h2; uint32_t u; } cvt;
    cvt.h2 = h;
    return cvt.u;
}

#define CP_ASYNC16(dst, src) \
    asm volatile("cp.async.cg.shared.global [%0], [%1], 16;" :: "r"(dst), "l"(src))
#define CP_COMMIT() asm volatile("cp.async.commit_group;" ::: "memory")
#define CP_WAIT(n)  asm volatile("cp.async.wait_group %0;" :: "n"(n) : "memory")

// m16n8k16 f16 inputs, f32 accumulate
__device__ __forceinline__ void mma_f16(float* d, const uint32_t* a, const uint32_t* b) {
    asm volatile(
        "mma.sync.aligned.m16n8k16.row.col.f32.f16.f16.f32 "
        "{%0,%1,%2,%3}, {%4,%5,%6,%7}, {%8,%9}, {%0,%1,%2,%3};"
        : "+f"(d[0]), "+f"(d[1]), "+f"(d[2]), "+f"(d[3])
        : "r"(a[0]), "r"(a[1]), "r"(a[2]), "r"(a[3]), "r"(b[0]), "r"(b[1]));
}

// ---------------------------------------------------------------------------
// Weight transpose+convert: out_h[N,K] = (half) in_f[K,N]
// grid(N/32, K/32), block(32,8)
// ---------------------------------------------------------------------------
__global__ void wconv_kernel(const float* __restrict__ in, __half* __restrict__ out,
                             int K, int N) {
    __shared__ float tile[32][33];
    int n0 = blockIdx.x * 32, k0 = blockIdx.y * 32;
#pragma unroll
    for (int i = threadIdx.y; i < 32; i += 8)
        tile[i][threadIdx.x] = in[(size_t)(k0 + i) * N + n0 + threadIdx.x];
    __syncthreads();
#pragma unroll
    for (int i = threadIdx.y; i < 32; i += 8)
        out[(size_t)(n0 + i) * K + k0 + threadIdx.x] = __float2half_rn(tile[threadIdx.x][i]);
}

// ---------------------------------------------------------------------------
// V transpose (fp16): g_vt[b][h][d][t] = qkv_v[b][t][h][d]
// grid(T/32, B*H*2), block(32,8)
// ---------------------------------------------------------------------------
__global__ void vt_kernel(const __half* __restrict__ qkv, __half* __restrict__ vt) {
    __shared__ __half tile[32][34];
    int t0 = blockIdx.x * 32;
    int by = blockIdx.y;
    int bh = by >> 1, dt = by & 1;
    int d0 = dt * 32;
    int b = bh / H_, h = bh % H_;
    const __half* src = qkv + (size_t)b * T_ * 3 * C_ + 2 * C_ + h * HD_;
#pragma unroll
    for (int i = threadIdx.y; i < 32; i += 8)
        tile[i][threadIdx.x] = src[(size_t)(t0 + i) * 3 * C_ + d0 + threadIdx.x];
    __syncthreads();
    __half* dst = vt + (size_t)bh * HD_ * T_;
#pragma unroll
    for (int i = threadIdx.y; i < 32; i += 8)
        dst[(size_t)(d0 + i) * T_ + t0 + threadIdx.x] = tile[threadIdx.x][i];
}

// ---------------------------------------------------------------------------
// LayerNorm: one block (256 thr) per row of 768.  Output fp16.
// ---------------------------------------------------------------------------
__global__ void ln_kernel(const float* __restrict__ x, const float* __restrict__ g,
                          const float* __restrict__ b, __half* __restrict__ out) {
    int row = blockIdx.x;
    const float* xr = x + (size_t)row * C_;
    float v[3];
    float s = 0.f, sq = 0.f;
#pragma unroll
    for (int i = 0; i < 3; i++) {
        v[i] = xr[threadIdx.x + i * 256];
        s += v[i];
        sq += v[i] * v[i];
    }
#pragma unroll
    for (int off = 16; off; off >>= 1) {
        s  += __shfl_xor_sync(0xffffffffu, s, off);
        sq += __shfl_xor_sync(0xffffffffu, sq, off);
    }
    __shared__ float ss[8], ssq[8];
    int w = threadIdx.x >> 5, lane = threadIdx.x & 31;
    if (lane == 0) { ss[w] = s; ssq[w] = sq; }
    __syncthreads();
    if (w == 0) {
        s = ss[lane & 7];
        sq = ssq[lane & 7];
#pragma unroll
        for (int off = 4; off; off >>= 1) {
            s  += __shfl_xor_sync(0xffffffffu, s, off);
            sq += __shfl_xor_sync(0xffffffffu, sq, off);
        }
        if (lane == 0) { ss[0] = s; ssq[0] = sq; }
    }
    __syncthreads();
    float mean = ss[0] * (1.0f / C_);
    float var  = ssq[0] * (1.0f / C_) - mean * mean;
    float rstd = rsqrtf(var + 1e-5f);
    __half* outr = out + (size_t)row * C_;
#pragma unroll
    for (int i = 0; i < 3; i++) {
        int c = threadIdx.x + i * 256;
        outr[c] = __float2half_rn((v[i] - mean) * rstd * g[c] + b[c]);
    }
}

// ---------------------------------------------------------------------------
// f16 GEMM: C[M,N] = A[M,K] @ Wt[N,K]^T, both fp16 K-major, fp32 accumulate.
// BM=BN=128, BK=64, 3-stage cp.async, 256 threads (8 warps, 64x32 each).
// EPI: 0 = half out, 1 = float out += res, 2 = GELU -> half out
// ---------------------------------------------------------------------------
#define STAGE_BYTES 32768               // A 16KB + B 16KB
#define GEMM_SMEM (3 * STAGE_BYTES)     // 96KB

__device__ __forceinline__ void load_stage(uint32_t sa, uint32_t sb,
                                           const __half* __restrict__ Ab,
                                           const __half* __restrict__ Wb,
                                           int K, int kb, int tid) {
    int k0 = kb * 64;
#pragma unroll
    for (int t = 0; t < 4; t++) {
        int linear = tid + t * 256;         // 0..1023
        int m = linear >> 3, c = linear & 7;
        uint32_t sw = (uint32_t)((m * 32 + ((c * 4) ^ ((m & 7) << 2))) * 4);
        CP_ASYNC16(sa + sw, Ab + (size_t)m * K + k0 + c * 8);
        CP_ASYNC16(sb + sw, Wb + (size_t)m * K + k0 + c * 8);
    }
}

template <int EPI>
__global__ __launch_bounds__(256, 2)
void tc_gemm(const __half* __restrict__ A, const __half* __restrict__ Wt,
             const float* __restrict__ res, void* __restrict__ Cm,
             int M, int N, int K) {
    extern __shared__ __align__(16) char dsm[];
    uint32_t sbase = smem_u32(dsm);

    int tid = threadIdx.x;
    int wid = tid >> 5, lane = tid & 31;
    int warp_m = wid >> 2, warp_n = wid & 3;
    int lr = lane >> 2, lc = lane & 3;
    const int KB = K >> 6;

    const __half* Ab = A + (size_t)blockIdx.y * 128 * K;
    const __half* Wb = Wt + (size_t)blockIdx.x * 128 * K;

    float acc[4][4][4];
#pragma unroll
    for (int i = 0; i < 4; i++)
#pragma unroll
        for (int j = 0; j < 4; j++)
#pragma unroll
            for (int r = 0; r < 4; r++) acc[i][j][r] = 0.f;

    load_stage(sbase, sbase + 16384, Ab, Wb, K, 0, tid);
    CP_COMMIT();
    load_stage(sbase + STAGE_BYTES, sbase + STAGE_BYTES + 16384, Ab, Wb, K, 1, tid);
    CP_COMMIT();

    for (int kb = 0; kb < KB; kb++) {
        int s = kb % 3;
        if (kb + 1 < KB) { CP_WAIT(1); } else { CP_WAIT(0); }
        __syncthreads();
        if (kb + 2 < KB) {
            int sn = (kb + 2) % 3;
            load_stage(sbase + sn * STAGE_BYTES, sbase + sn * STAGE_BYTES + 16384,
                       Ab, Wb, K, kb + 2, tid);
            CP_COMMIT();
        }

        const uint32_t* as32 = (const uint32_t*)(dsm + s * STAGE_BYTES);
        const uint32_t* bs32 = (const uint32_t*)(dsm + s * STAGE_BYTES + 16384);
#pragma unroll
        for (int ks = 0; ks < 4; ks++) {
            int p = ks * 8 + lc;
            uint32_t afr[4][4], bfr[4][2];
#pragma unroll
            for (int mt = 0; mt < 4; mt++) {
                int r0 = warp_m * 64 + mt * 16 + lr;
                int sw = (r0 & 7) << 2;
                afr[mt][0] = as32[r0 * 32 + (p ^ sw)];
                afr[mt][1] = as32[(r0 + 8) * 32 + (p ^ sw)];
                afr[mt][2] = as32[r0 * 32 + ((p + 4) ^ sw)];
                afr[mt][3] = as32[(r0 + 8) * 32 + ((p + 4) ^ sw)];
            }
#pragma unroll
            for (int nt = 0; nt < 4; nt++) {
                int n0 = warp_n * 32 + nt * 8 + lr;
                int sw = (n0 & 7) << 2;
                bfr[nt][0] = bs32[n0 * 32 + (p ^ sw)];
                bfr[nt][1] = bs32[n0 * 32 + ((p + 4) ^ sw)];
            }
#pragma unroll
            for (int mt = 0; mt < 4; mt++)
#pragma unroll
                for (int nt = 0; nt < 4; nt++)
                    mma_f16(acc[mt][nt], afr[mt], bfr[nt]);
        }
    }

    __syncthreads();
    int gm0 = blockIdx.y * 128 + warp_m * 64;
    int gn0 = blockIdx.x * 128 + warp_n * 32;
#pragma unroll
    for (int mt = 0; mt < 4; mt++) {
#pragma unroll
        for (int nt = 0; nt < 4; nt++) {
            int gm = gm0 + mt * 16 + lr;
            int gn = gn0 + nt * 8 + lc * 2;
#pragma unroll
            for (int half_ = 0; half_ < 2; half_++) {
                int row = gm + half_ * 8;
                size_t off = (size_t)row * N + gn;
                float vx = acc[mt][nt][half_ * 2 + 0];
                float vy = acc[mt][nt][half_ * 2 + 1];
                if (EPI == 1) {
                    float2 rs = *(const float2*)(res + off);
                    float2 v = make_float2(vx + rs.x, vy + rs.y);
                    *(float2*)((float*)Cm + off) = v;
                } else if (EPI == 2) {
                    vx = 0.5f * vx * (1.0f + erff(vx * 0.7071067811865475f));
                    vy = 0.5f * vy * (1.0f + erff(vy * 0.7071067811865475f));
                    *(__half2*)((__half*)Cm + off) = __floats2half2_rn(vx, vy);
                } else {
                    *(__half2*)((__half*)Cm + off) = __floats2half2_rn(vx, vy);
                }
            }
        }
    }
}

// ---------------------------------------------------------------------------
// Tensor-core flash attention (fp16 in / fp32 accum, causal).
// Grid: (T/64, B*H), 128 threads, reverse-qb for causal load balance.
// smem halfs: Q [0,4096) | P [4096,8192) | K[2] [8192,16384) | V[2] [16384,24576)
// ---------------------------------------------------------------------------
#define ATTN_SMEM (24576 * 2)   // 48KB

__device__ __forceinline__ void attn_load_kv(uint32_t sb, const __half* __restrict__ kbase,
                                             const __half* __restrict__ vtb,
                                             int j, int s, int tid) {
    uint32_t kdst = sb + (uint32_t)(8192 + s * 4096) * 2;
    uint32_t vdst = sb + (uint32_t)(16384 + s * 4096) * 2;
#pragma unroll
    for (int t = 0; t < 4; t++) {
        int linear = tid + t * 128;       // 0..511
        int r = linear >> 3, c = linear & 7;
        uint32_t sw = (uint32_t)((r * 32 + ((c * 4) ^ ((r & 7) << 2))) * 4);
        CP_ASYNC16(kdst + sw, kbase + (size_t)(j * 64 + r) * 3 * C_ + c * 8);
        CP_ASYNC16(vdst + sw, vtb + (size_t)r * T_ + j * 64 + c * 8);
    }
}

__global__ __launch_bounds__(128, 2)
void attn_tc(const __half* __restrict__ qkv, const __half* __restrict__ vt,
             __half* __restrict__ y) {
    extern __shared__ __align__(16) char smc[];
    uint32_t sb = smem_u32(smc);
    uint32_t* s32 = (uint32_t*)smc;       // word view

    int qb = gridDim.x - 1 - blockIdx.x;  // longest blocks first
    int bh = blockIdx.y;
    int b = bh / H_, h = bh % H_;
    int tid = threadIdx.x, wid = tid >> 5, lane = tid & 31;
    int lr = lane >> 2, lc = lane & 3;

    const __half* qbase = qkv + (size_t)b * T_ * 3 * C_ + h * HD_;
    const __half* kbase = qbase + C_;
    const __half* vtb = vt + (size_t)bh * HD_ * T_;

    // load Q tile (64 rows x 64 halfs)
#pragma unroll
    for (int t = 0; t < 4; t++) {
        int linear = tid + t * 128;
        int r = linear >> 3, c = linear & 7;
        uint32_t sw = (uint32_t)((r * 32 + ((c * 4) ^ ((r & 7) << 2))) * 4);
        CP_ASYNC16(sb + sw, qbase + (size_t)(qb * 64 + r) * 3 * C_ + c * 8);
    }
    CP_COMMIT();
    attn_load_kv(sb, kbase, vtb, 0, 0, tid);
    CP_COMMIT();

    CP_WAIT(1);
    __syncthreads();

    int r0 = wid * 16 + lr;
    int swq = (r0 & 7) << 2;
    uint32_t qfr[4][4];
#pragma unroll
    for (int ks = 0; ks < 4; ks++) {
        int p = ks * 8 + lc;
        qfr[ks][0] = s32[r0 * 32 + (p ^ swq)];
        qfr[ks][1] = s32[(r0 + 8) * 32 + (p ^ swq)];
        qfr[ks][2] = s32[r0 * 32 + ((p + 4) ^ swq)];
        qfr[ks][3] = s32[(r0 + 8) * 32 + ((p + 4) ^ swq)];
    }

    float oacc[8][4];
#pragma unroll
    for (int i = 0; i < 8; i++)
#pragma unroll
        for (int e = 0; e < 4; e++) oacc[i][e] = 0.f;
    float m0 = -1e30f, m1 = -1e30f, l0 = 0.f, l1 = 0.f;

    int rg0 = qb * 64 + r0;
    uint32_t* p32 = s32 + 2048;           // P region

    for (int j = 0; j <= qb; j++) {
        int s = j & 1;
        if (j < qb) {
            attn_load_kv(sb, kbase, vtb, j + 1, s ^ 1, tid);
            CP_COMMIT();
            CP_WAIT(1);
        } else {
            CP_WAIT(0);
        }
        __syncthreads();

        const uint32_t* ksm = s32 + 4096 + s * 2048;
        const uint32_t* vsm = s32 + 8192 + s * 2048;

        // S = Q @ K^T
        float sacc[8][4];
#pragma unroll
        for (int nf = 0; nf < 8; nf++)
#pragma unroll
            for (int e = 0; e < 4; e++) sacc[nf][e] = 0.f;
#pragma unroll
        for (int nf = 0; nf < 8; nf++) {
            int n0 = nf * 8 + lr;
            int sw = (n0 & 7) << 2;
#pragma unroll
            for (int ks = 0; ks < 4; ks++) {
                int p = ks * 8 + lc;
                uint32_t bfr[2];
                bfr[0] = ksm[n0 * 32 + (p ^ sw)];
                bfr[1] = ksm[n0 * 32 + ((p + 4) ^ sw)];
                mma_f16(sacc[nf], qfr[ks], bfr);
            }
        }

        // scale + causal mask (diagonal tile only)
#pragma unroll
        for (int nf = 0; nf < 8; nf++) {
#pragma unroll
            for (int e = 0; e < 4; e++) {
                float v = sacc[nf][e] * 0.125f;
                if (j == qb) {
                    int col = j * 64 + nf * 8 + 2 * lc + (e & 1);
                    int row = (e < 2) ? rg0 : rg0 + 8;
                    if (col > row) v = -1e30f;
                }
                sacc[nf][e] = v;
            }
        }

        // online softmax (rows lr, lr+8; 4 lanes/quad share a row)
        float ml0 = -1e30f, ml1 = -1e30f;
#pragma unroll
        for (int nf = 0; nf < 8; nf++) {
            ml0 = fmaxf(ml0, fmaxf(sacc[nf][0], sacc[nf][1]));
            ml1 = fmaxf(ml1, fmaxf(sacc[nf][2], sacc[nf][3]));
        }
#pragma unroll
        for (int off = 1; off < 4; off <<= 1) {
            ml0 = fmaxf(ml0, __shfl_xor_sync(0xffffffffu, ml0, off));
            ml1 = fmaxf(ml1, __shfl_xor_sync(0xffffffffu, ml1, off));
        }
        float mn0 = fmaxf(m0, ml0), mn1 = fmaxf(m1, ml1);
        float c0 = __expf(m0 - mn0), c1 = __expf(m1 - mn1);
        float ls0 = 0.f, ls1 = 0.f;
#pragma unroll
        for (int nf = 0; nf < 8; nf++) {
            float p0 = __expf(sacc[nf][0] - mn0);
            float p1 = __expf(sacc[nf][1] - mn0);
            float p2 = __expf(sacc[nf][2] - mn1);
            float p3 = __expf(sacc[nf][3] - mn1);
            ls0 += p0 + p1;
            ls1 += p2 + p3;
            int wp = nf * 4 + lc;     // word index of col pair within row
            p32[r0 * 32 + (wp ^ swq)]       = h2_as_u32(__floats2half2_rn(p0, p1));
            p32[(r0 + 8) * 32 + (wp ^ swq)] = h2_as_u32(__floats2half2_rn(p2, p3));
        }
#pragma unroll
        for (int off = 1; off < 4; off <<= 1) {
            ls0 += __shfl_xor_sync(0xffffffffu, ls0, off);
            ls1 += __shfl_xor_sync(0xffffffffu, ls1, off);
        }
        l0 = l0 * c0 + ls0;
        l1 = l1 * c1 + ls1;
        m0 = mn0; m1 = mn1;
#pragma unroll
        for (int nf = 0; nf < 8; nf++) {
            oacc[nf][0] *= c0;
            oacc[nf][1] *= c0;
            oacc[nf][2] *= c1;
            oacc[nf][3] *= c1;
        }
        __syncwarp();

        // O += P @ V  (A = P from this warp's own rows, B = Vt)
#pragma unroll
        for (int ks = 0; ks < 4; ks++) {
            int p = ks * 8 + lc;
            uint32_t pafr[4];
            pafr[0] = p32[r0 * 32 + (p ^ swq)];
            pafr[1] = p32[(r0 + 8) * 32 + (p ^ swq)];
            pafr[2] = p32[r0 * 32 + ((p + 4) ^ swq)];
            pafr[3] = p32[(r0 + 8) * 32 + ((p + 4) ^ swq)];
#pragma unroll
            for (int nf = 0; nf < 8; nf++) {
                int n0 = nf * 8 + lr;
                int sw = (n0 & 7) << 2;
                uint32_t bfr[2];
                bfr[0] = vsm[n0 * 32 + (p ^ sw)];
                bfr[1] = vsm[n0 * 32 + ((p + 4) ^ sw)];
                mma_f16(oacc[nf], pafr, bfr);
            }
        }
        __syncthreads();
    }

    // write y (fp16)
    float inv0 = 1.0f / l0, inv1 = 1.0f / l1;
#pragma unroll
    for (int nf = 0; nf < 8; nf++) {
        int gc = h * HD_ + nf * 8 + 2 * lc;
        size_t o0 = (size_t)(b * T_ + rg0) * C_ + gc;
        size_t o1 = (size_t)(b * T_ + rg0 + 8) * C_ + gc;
        *(__half2*)(y + o0) = __floats2half2_rn(oacc[nf][0] * inv0, oacc[nf][1] * inv0);
        *(__half2*)(y + o1) = __floats2half2_rn(oacc[nf][2] * inv1, oacc[nf][3] * inv1);
    }
}

// ---------------------------------------------------------------------------
// Launch
// ---------------------------------------------------------------------------
extern "C" void kernel_launch(void* const* d_in, const int* in_sizes, int n_in,
                              void* d_out, int out_size) {
    const float* x       = (const float*)d_in[0];
    const float* ln1_g   = (const float*)d_in[1];
    const float* ln1_b   = (const float*)d_in[2];
    const float* W_qkv   = (const float*)d_in[3];
    const float* W_attn  = (const float*)d_in[4];
    const float* ln2_g   = (const float*)d_in[5];
    const float* ln2_b   = (const float*)d_in[6];
    const float* W_fc    = (const float*)d_in[7];
    const float* W_mlp   = (const float*)d_in[8];
    float* out = (float*)d_out;

    __half *ln, *qkv, *vtb, *yb, *hb, *wq, *wa, *wf, *wm;
    float* x1;
    cudaGetSymbolAddress((void**)&ln, g_ln);
    cudaGetSymbolAddress((void**)&qkv, g_qkv);
    cudaGetSymbolAddress((void**)&vtb, g_vt);
    cudaGetSymbolAddress((void**)&yb, g_y);
    cudaGetSymbolAddress((void**)&x1, g_x1);
    cudaGetSymbolAddress((void**)&hb, g_h);
    cudaGetSymbolAddress((void**)&wq, g_wq);
    cudaGetSymbolAddress((void**)&wa, g_wa);
    cudaGetSymbolAddress((void**)&wf, g_wf);
    cudaGetSymbolAddress((void**)&wm, g_wm);

    cudaFuncSetAttribute(tc_gemm<0>, cudaFuncAttributeMaxDynamicSharedMemorySize, GEMM_SMEM);
    cudaFuncSetAttribute(tc_gemm<1>, cudaFuncAttributeMaxDynamicSharedMemorySize, GEMM_SMEM);
    cudaFuncSetAttribute(tc_gemm<2>, cudaFuncAttributeMaxDynamicSharedMemorySize, GEMM_SMEM);
    cudaFuncSetAttribute(attn_tc, cudaFuncAttributeMaxDynamicSharedMemorySize, ATTN_SMEM);

    // 0) weights -> fp16 [N,K]
    wconv_kernel<<<dim3(3 * C_ / 32, C_ / 32), dim3(32, 8)>>>(W_qkv, wq, C_, 3 * C_);
    wconv_kernel<<<dim3(C_ / 32, C_ / 32), dim3(32, 8)>>>(W_attn, wa, C_, C_);
    wconv_kernel<<<dim3(4 * C_ / 32, C_ / 32), dim3(32, 8)>>>(W_fc, wf, C_, 4 * C_);
    wconv_kernel<<<dim3(C_ / 32, 4 * C_ / 32), dim3(32, 8)>>>(W_mlp, wm, 4 * C_, C_);

    // 1) LN1 -> fp16
    ln_kernel<<<BT_, 256>>>(x, ln1_g, ln1_b, ln);
    // 2) QKV = ln1 @ W_qkv -> fp16
    tc_gemm<0><<<dim3(3 * C_ / 128, BT_ / 128), 256, GEMM_SMEM>>>(ln, wq, nullptr, qkv,
                                                                  BT_, 3 * C_, C_);
    // 3) V transpose (fp16)
    vt_kernel<<<dim3(T_ / 32, B_ * H_ * 2), dim3(32, 8)>>>(qkv, vtb);
    // 4) causal flash attention (fp16 mma)
    attn_tc<<<dim3(T_ / 64, B_ * H_), 128, ATTN_SMEM>>>(qkv, vtb, yb);
    // 5) x1 = x + y @ W_attn_proj (fp32 out)
    tc_gemm<1><<<dim3(C_ / 128, BT_ / 128), 256, GEMM_SMEM>>>(yb, wa, x, x1,
                                                              BT_, C_, C_);
    // 6) LN2 -> fp16
    ln_kernel<<<BT_, 256>>>(x1, ln2_g, ln2_b, ln);
    // 7) h = gelu(ln2 @ W_fc) -> fp16
    tc_gemm<2><<<dim3(4 * C_ / 128, BT_ / 128), 256, GEMM_SMEM>>>(ln, wf, nullptr, hb,
                                                                  BT_, 4 * C_, C_);
    // 8) out = x1 + h @ W_mlp_proj (fp32 out)
    tc_gemm<1><<<dim3(C_ / 128, BT_ / 128), 256, GEMM_SMEM>>>(hb, wm, x1, out,
                                                              BT_, C_, 4 * C_);
}

// round 12
// speedup vs baseline: 1.7589x; 1.0470x over previous
#include <cuda_runtime.h>
#include <cuda_fp16.h>
#include <math.h>
#include <stdint.h>

// Problem constants
#define B_ 2
#define T_ 2048
#define C_ 768
#define H_ 12
#define HD_ 64
#define BT_ (B_ * T_)   // 4096

// ---------------------------------------------------------------------------
// Scratch (device globals; no allocation allowed)
// ---------------------------------------------------------------------------
__device__ __half g_ln[BT_ * C_];            // LN output (fp16)
__device__ __half g_qkv[BT_ * 3 * C_];       // QKV (fp16)
__device__ __half g_vt[B_ * H_ * HD_ * T_];  // V transposed [b][h][d][t] fp16
__device__ __half g_y[BT_ * C_];             // attention output (fp16)
__device__ float  g_x1[BT_ * C_];            // x + attn (fp32)
__device__ __half g_h[BT_ * 4 * C_];         // gelu(fc) (fp16)
// fp16 transposed weights [N,K]
__device__ __half g_wq[3 * C_ * C_];
__device__ __half g_wa[C_ * C_];
__device__ __half g_wf[4 * C_ * C_];
__device__ __half g_wm[C_ * 4 * C_];

// ---------------------------------------------------------------------------
// Helpers
// ---------------------------------------------------------------------------
__device__ __forceinline__ uint32_t smem_u32(const void* p) {
    uint32_t a;
    asm("{ .reg .u64 t; cvta.to.shared.u64 t, %1; cvt.u32.u64 %0, t; }"
        : "=r"(a) : "l"(p));
    return a;
}

__device__ __forceinline__ uint32_t h2_as_u32(__half2 h) {
    union { __half2 h2; uint32_t u; } cvt;
    cvt.h2 = h;
    return cvt.u;
}

#define CP_ASYNC16(dst, src) \
    asm volatile("cp.async.cg.shared.global [%0], [%1], 16;" :: "r"(dst), "l"(src))
#define CP_COMMIT() asm volatile("cp.async.commit_group;" ::: "memory")
#define CP_WAIT(n)  asm volatile("cp.async.wait_group %0;" :: "n"(n) : "memory")

// m16n8k16 f16 inputs, f32 accumulate
__device__ __forceinline__ void mma_f16(float* d, const uint32_t* a, const uint32_t* b) {
    asm volatile(
        "mma.sync.aligned.m16n8k16.row.col.f32.f16.f16.f32 "
        "{%0,%1,%2,%3}, {%4,%5,%6,%7}, {%8,%9}, {%0,%1,%2,%3};"
        : "+f"(d[0]), "+f"(d[1]), "+f"(d[2]), "+f"(d[3])
        : "r"(a[0]), "r"(a[1]), "r"(a[2]), "r"(a[3]), "r"(b[0]), "r"(b[1]));
}

// ---------------------------------------------------------------------------
// Fused weight transpose+convert (all four weights, one launch).
// Each 32x32 tile: out_h[N,K] = (half) in_f[K,N].  block(32,8)
// Tile counts: qkv 72x24=1728 | attn 24x24=576 | fc 96x24=2304 | mlp 24x96=2304
// ---------------------------------------------------------------------------
#define WT_QKV 1728
#define WT_A   576
#define WT_FC  2304
#define WT_MLP 2304
#define WT_TOT (WT_QKV + WT_A + WT_FC + WT_MLP)

__global__ void wconv_all(const float* __restrict__ iq, const float* __restrict__ ia,
                          const float* __restrict__ ifc, const float* __restrict__ im,
                          __half* __restrict__ oq, __half* __restrict__ oa,
                          __half* __restrict__ ofc, __half* __restrict__ om) {
    __shared__ float tile[32][33];
    int t = blockIdx.x;
    const float* in;
    __half* out;
    int K, N;
    if (t < WT_QKV) { in = iq; out = oq; K = C_; N = 3 * C_; }
    else if (t < WT_QKV + WT_A) { t -= WT_QKV; in = ia; out = oa; K = C_; N = C_; }
    else if (t < WT_QKV + WT_A + WT_FC) { t -= WT_QKV + WT_A; in = ifc; out = ofc; K = C_; N = 4 * C_; }
    else { t -= WT_QKV + WT_A + WT_FC; in = im; out = om; K = 4 * C_; N = C_; }
    int tiles_n = N >> 5;
    int n0 = (t % tiles_n) << 5, k0 = (t / tiles_n) << 5;
#pragma unroll
    for (int i = threadIdx.y; i < 32; i += 8)
        tile[i][threadIdx.x] = in[(size_t)(k0 + i) * N + n0 + threadIdx.x];
    __syncthreads();
#pragma unroll
    for (int i = threadIdx.y; i < 32; i += 8)
        out[(size_t)(n0 + i) * K + k0 + threadIdx.x] = __float2half_rn(tile[threadIdx.x][i]);
}

// ---------------------------------------------------------------------------
// V transpose (fp16): g_vt[b][h][d][t] = qkv_v[b][t][h][d]
// grid(T/32, B*H*2), block(32,8)
// ---------------------------------------------------------------------------
__global__ void vt_kernel(const __half* __restrict__ qkv, __half* __restrict__ vt) {
    __shared__ __half tile[32][34];
    int t0 = blockIdx.x * 32;
    int by = blockIdx.y;
    int bh = by >> 1, dt = by & 1;
    int d0 = dt * 32;
    int b = bh / H_, h = bh % H_;
    const __half* src = qkv + (size_t)b * T_ * 3 * C_ + 2 * C_ + h * HD_;
#pragma unroll
    for (int i = threadIdx.y; i < 32; i += 8)
        tile[i][threadIdx.x] = src[(size_t)(t0 + i) * 3 * C_ + d0 + threadIdx.x];
    __syncthreads();
    __half* dst = vt + (size_t)bh * HD_ * T_;
#pragma unroll
    for (int i = threadIdx.y; i < 32; i += 8)
        dst[(size_t)(d0 + i) * T_ + t0 + threadIdx.x] = tile[threadIdx.x][i];
}

// ---------------------------------------------------------------------------
// LayerNorm: warp per row, float4, warp-only reduction. Output fp16.
// grid BT_/8, block 256 (8 warps).
// ---------------------------------------------------------------------------
__global__ void ln_kernel(const float* __restrict__ x, const float* __restrict__ g,
                          const float* __restrict__ b, __half* __restrict__ out) {
    int row = blockIdx.x * 8 + (threadIdx.x >> 5);
    int lane = threadIdx.x & 31;
    const float4* xr = (const float4*)(x + (size_t)row * C_);
    float4 v[6];
    float s = 0.f, sq = 0.f;
#pragma unroll
    for (int i = 0; i < 6; i++) {
        v[i] = xr[lane + i * 32];
        s  += v[i].x + v[i].y + v[i].z + v[i].w;
        sq += v[i].x * v[i].x + v[i].y * v[i].y + v[i].z * v[i].z + v[i].w * v[i].w;
    }
#pragma unroll
    for (int off = 16; off; off >>= 1) {
        s  += __shfl_xor_sync(0xffffffffu, s, off);
        sq += __shfl_xor_sync(0xffffffffu, sq, off);
    }
    float mean = s * (1.0f / C_);
    float var  = sq * (1.0f / C_) - mean * mean;
    float rstd = rsqrtf(var + 1e-5f);
    const float4* g4 = (const float4*)g;
    const float4* b4 = (const float4*)b;
    uint2* o8 = (uint2*)(out + (size_t)row * C_);
#pragma unroll
    for (int i = 0; i < 6; i++) {
        int idx = lane + i * 32;
        float4 gv = g4[idx], bv = b4[idx];
        float r0 = (v[i].x - mean) * rstd * gv.x + bv.x;
        float r1 = (v[i].y - mean) * rstd * gv.y + bv.y;
        float r2 = (v[i].z - mean) * rstd * gv.z + bv.z;
        float r3 = (v[i].w - mean) * rstd * gv.w + bv.w;
        uint2 u;
        u.x = h2_as_u32(__floats2half2_rn(r0, r1));
        u.y = h2_as_u32(__floats2half2_rn(r2, r3));
        o8[idx] = u;
    }
}

// ---------------------------------------------------------------------------
// f16 GEMM: C[M,N] = A[M,K] @ Wt[N,K]^T, fp16 in, fp32 accumulate.
// BM=128, BN template (128 or 64), BK=64, 3-stage cp.async, 256 threads.
// BN=128: 8 warps 64x32 (MT=4). BN=64: 8 warps 32x32 (MT=2).
// EPI: 0 = half out, 1 = float out += res, 2 = GELU -> half out
// ---------------------------------------------------------------------------
#define A_STAGE_BYTES 16384
template <int BN> struct GemmCfg {
    static const int B_STAGE_BYTES = BN * 128;          // BN rows x 64 halfs
    static const int STAGE_BYTES = A_STAGE_BYTES + B_STAGE_BYTES;
    static const int SMEM = 3 * STAGE_BYTES;
    static const int MT = (BN == 128) ? 4 : 2;
};

template <int BN>
__device__ __forceinline__ void load_stage(uint32_t sa, uint32_t sb,
                                           const __half* __restrict__ Ab,
                                           const __half* __restrict__ Wb,
                                           int K, int kb, int tid) {
    int k0 = kb * 64;
#pragma unroll
    for (int t = 0; t < 4; t++) {
        int linear = tid + t * 256;         // 0..1023
        int m = linear >> 3, c = linear & 7;
        uint32_t sw = (uint32_t)((m * 32 + ((c * 4) ^ ((m & 7) << 2))) * 4);
        CP_ASYNC16(sa + sw, Ab + (size_t)m * K + k0 + c * 8);
    }
#pragma unroll
    for (int t = 0; t < BN / 32; t++) {
        int linear = tid + t * 256;         // 0..BN*8-1
        int m = linear >> 3, c = linear & 7;
        uint32_t sw = (uint32_t)((m * 32 + ((c * 4) ^ ((m & 7) << 2))) * 4);
        CP_ASYNC16(sb + sw, Wb + (size_t)m * K + k0 + c * 8);
    }
}

template <int EPI, int BN>
__global__ __launch_bounds__(256, 2)
void tc_gemm(const __half* __restrict__ A, const __half* __restrict__ Wt,
             const float* __restrict__ res, void* __restrict__ Cm,
             int M, int N, int K) {
    typedef GemmCfg<BN> CFG;
    const int MT = CFG::MT;
    extern __shared__ __align__(16) char dsm[];
    uint32_t sbase = smem_u32(dsm);

    int tid = threadIdx.x;
    int wid = tid >> 5, lane = tid & 31;
    int warp_m, warp_n;
    if (BN == 128) { warp_m = wid >> 2; warp_n = wid & 3; }
    else           { warp_m = wid >> 1; warp_n = wid & 1; }
    int lr = lane >> 2, lc = lane & 3;
    const int KB = K >> 6;

    const __half* Ab = A + (size_t)blockIdx.y * 128 * K;
    const __half* Wb = Wt + (size_t)blockIdx.x * BN * K;

    float acc[CFG::MT][4][4];
#pragma unroll
    for (int i = 0; i < MT; i++)
#pragma unroll
        for (int j = 0; j < 4; j++)
#pragma unroll
            for (int r = 0; r < 4; r++) acc[i][j][r] = 0.f;

    load_stage<BN>(sbase, sbase + A_STAGE_BYTES, Ab, Wb, K, 0, tid);
    CP_COMMIT();
    load_stage<BN>(sbase + CFG::STAGE_BYTES, sbase + CFG::STAGE_BYTES + A_STAGE_BYTES,
                   Ab, Wb, K, 1, tid);
    CP_COMMIT();

    for (int kb = 0; kb < KB; kb++) {
        int s = kb % 3;
        if (kb + 1 < KB) { CP_WAIT(1); } else { CP_WAIT(0); }
        __syncthreads();
        if (kb + 2 < KB) {
            int sn = (kb + 2) % 3;
            load_stage<BN>(sbase + sn * CFG::STAGE_BYTES,
                           sbase + sn * CFG::STAGE_BYTES + A_STAGE_BYTES,
                           Ab, Wb, K, kb + 2, tid);
            CP_COMMIT();
        }

        const uint32_t* as32 = (const uint32_t*)(dsm + s * CFG::STAGE_BYTES);
        const uint32_t* bs32 = (const uint32_t*)(dsm + s * CFG::STAGE_BYTES + A_STAGE_BYTES);
#pragma unroll
        for (int ks = 0; ks < 4; ks++) {
            int p = ks * 8 + lc;
            uint32_t afr[CFG::MT][4], bfr[4][2];
#pragma unroll
            for (int mt = 0; mt < MT; mt++) {
                int r0 = warp_m * (MT * 16) + mt * 16 + lr;
                int sw = (r0 & 7) << 2;
                afr[mt][0] = as32[r0 * 32 + (p ^ sw)];
                afr[mt][1] = as32[(r0 + 8) * 32 + (p ^ sw)];
                afr[mt][2] = as32[r0 * 32 + ((p + 4) ^ sw)];
                afr[mt][3] = as32[(r0 + 8) * 32 + ((p + 4) ^ sw)];
            }
#pragma unroll
            for (int nt = 0; nt < 4; nt++) {
                int n0 = warp_n * 32 + nt * 8 + lr;
                int sw = (n0 & 7) << 2;
                bfr[nt][0] = bs32[n0 * 32 + (p ^ sw)];
                bfr[nt][1] = bs32[n0 * 32 + ((p + 4) ^ sw)];
            }
#pragma unroll
            for (int mt = 0; mt < MT; mt++)
#pragma unroll
                for (int nt = 0; nt < 4; nt++)
                    mma_f16(acc[mt][nt], afr[mt], bfr[nt]);
        }
    }

    __syncthreads();
    int gm0 = blockIdx.y * 128 + warp_m * (MT * 16);
    int gn0 = blockIdx.x * BN + warp_n * 32;
#pragma unroll
    for (int mt = 0; mt < MT; mt++) {
#pragma unroll
        for (int nt = 0; nt < 4; nt++) {
            int gm = gm0 + mt * 16 + lr;
            int gn = gn0 + nt * 8 + lc * 2;
#pragma unroll
            for (int half_ = 0; half_ < 2; half_++) {
                int row = gm + half_ * 8;
                size_t off = (size_t)row * N + gn;
                float vx = acc[mt][nt][half_ * 2 + 0];
                float vy = acc[mt][nt][half_ * 2 + 1];
                if (EPI == 1) {
                    float2 rs = *(const float2*)(res + off);
                    float2 v = make_float2(vx + rs.x, vy + rs.y);
                    *(float2*)((float*)Cm + off) = v;
                } else if (EPI == 2) {
                    vx = 0.5f * vx * (1.0f + erff(vx * 0.7071067811865475f));
                    vy = 0.5f * vy * (1.0f + erff(vy * 0.7071067811865475f));
                    *(__half2*)((__half*)Cm + off) = __floats2half2_rn(vx, vy);
                } else {
                    *(__half2*)((__half*)Cm + off) = __floats2half2_rn(vx, vy);
                }
            }
        }
    }
}

// ---------------------------------------------------------------------------
// Tensor-core flash attention (fp16 in / fp32 accum, causal).
// Grid: (T/64, B*H), 128 threads, reverse-qb for causal load balance.
// smem halfs: Q [0,4096) | P [4096,8192) | K[2] [8192,16384) | V[2] [16384,24576)
// ---------------------------------------------------------------------------
#define ATTN_SMEM (24576 * 2)   // 48KB

__device__ __forceinline__ void attn_load_kv(uint32_t sb, const __half* __restrict__ kbase,
                                             const __half* __restrict__ vtb,
                                             int j, int s, int tid) {
    uint32_t kdst = sb + (uint32_t)(8192 + s * 4096) * 2;
    uint32_t vdst = sb + (uint32_t)(16384 + s * 4096) * 2;
#pragma unroll
    for (int t = 0; t < 4; t++) {
        int linear = tid + t * 128;       // 0..511
        int r = linear >> 3, c = linear & 7;
        uint32_t sw = (uint32_t)((r * 32 + ((c * 4) ^ ((r & 7) << 2))) * 4);
        CP_ASYNC16(kdst + sw, kbase + (size_t)(j * 64 + r) * 3 * C_ + c * 8);
        CP_ASYNC16(vdst + sw, vtb + (size_t)r * T_ + j * 64 + c * 8);
    }
}

__global__ __launch_bounds__(128, 2)
void attn_tc(const __half* __restrict__ qkv, const __half* __restrict__ vt,
             __half* __restrict__ y) {
    extern __shared__ __align__(16) char smc[];
    uint32_t sb = smem_u32(smc);
    uint32_t* s32 = (uint32_t*)smc;       // word view

    int qb = gridDim.x - 1 - blockIdx.x;  // longest blocks first
    int bh = blockIdx.y;
    int b = bh / H_, h = bh % H_;
    int tid = threadIdx.x, wid = tid >> 5, lane = tid & 31;
    int lr = lane >> 2, lc = lane & 3;

    const __half* qbase = qkv + (size_t)b * T_ * 3 * C_ + h * HD_;
    const __half* kbase = qbase + C_;
    const __half* vtb = vt + (size_t)bh * HD_ * T_;

    // load Q tile (64 rows x 64 halfs)
#pragma unroll
    for (int t = 0; t < 4; t++) {
        int linear = tid + t * 128;
        int r = linear >> 3, c = linear & 7;
        uint32_t sw = (uint32_t)((r * 32 + ((c * 4) ^ ((r & 7) << 2))) * 4);
        CP_ASYNC16(sb + sw, qbase + (size_t)(qb * 64 + r) * 3 * C_ + c * 8);
    }
    CP_COMMIT();
    attn_load_kv(sb, kbase, vtb, 0, 0, tid);
    CP_COMMIT();

    CP_WAIT(1);
    __syncthreads();

    int r0 = wid * 16 + lr;
    int swq = (r0 & 7) << 2;
    uint32_t qfr[4][4];
#pragma unroll
    for (int ks = 0; ks < 4; ks++) {
        int p = ks * 8 + lc;
        qfr[ks][0] = s32[r0 * 32 + (p ^ swq)];
        qfr[ks][1] = s32[(r0 + 8) * 32 + (p ^ swq)];
        qfr[ks][2] = s32[r0 * 32 + ((p + 4) ^ swq)];
        qfr[ks][3] = s32[(r0 + 8) * 32 + ((p + 4) ^ swq)];
    }

    float oacc[8][4];
#pragma unroll
    for (int i = 0; i < 8; i++)
#pragma unroll
        for (int e = 0; e < 4; e++) oacc[i][e] = 0.f;
    float m0 = -1e30f, m1 = -1e30f, l0 = 0.f, l1 = 0.f;

    int rg0 = qb * 64 + r0;
    uint32_t* p32 = s32 + 2048;           // P region

    for (int j = 0; j <= qb; j++) {
        int s = j & 1;
        if (j < qb) {
            attn_load_kv(sb, kbase, vtb, j + 1, s ^ 1, tid);
            CP_COMMIT();
            CP_WAIT(1);
        } else {
            CP_WAIT(0);
        }
        __syncthreads();

        const uint32_t* ksm = s32 + 4096 + s * 2048;
        const uint32_t* vsm = s32 + 8192 + s * 2048;

        // S = Q @ K^T
        float sacc[8][4];
#pragma unroll
        for (int nf = 0; nf < 8; nf++)
#pragma unroll
            for (int e = 0; e < 4; e++) sacc[nf][e] = 0.f;
#pragma unroll
        for (int nf = 0; nf < 8; nf++) {
            int n0 = nf * 8 + lr;
            int sw = (n0 & 7) << 2;
#pragma unroll
            for (int ks = 0; ks < 4; ks++) {
                int p = ks * 8 + lc;
                uint32_t bfr[2];
                bfr[0] = ksm[n0 * 32 + (p ^ sw)];
                bfr[1] = ksm[n0 * 32 + ((p + 4) ^ sw)];
                mma_f16(sacc[nf], qfr[ks], bfr);
            }
        }

        // scale + causal mask (diagonal tile only)
#pragma unroll
        for (int nf = 0; nf < 8; nf++) {
#pragma unroll
            for (int e = 0; e < 4; e++) {
                float v = sacc[nf][e] * 0.125f;
                if (j == qb) {
                    int col = j * 64 + nf * 8 + 2 * lc + (e & 1);
                    int row = (e < 2) ? rg0 : rg0 + 8;
                    if (col > row) v = -1e30f;
                }
                sacc[nf][e] = v;
            }
        }

        // online softmax (rows lr, lr+8; 4 lanes/quad share a row)
        float ml0 = -1e30f, ml1 = -1e30f;
#pragma unroll
        for (int nf = 0; nf < 8; nf++) {
            ml0 = fmaxf(ml0, fmaxf(sacc[nf][0], sacc[nf][1]));
            ml1 = fmaxf(ml1, fmaxf(sacc[nf][2], sacc[nf][3]));
        }
#pragma unroll
        for (int off = 1; off < 4; off <<= 1) {
            ml0 = fmaxf(ml0, __shfl_xor_sync(0xffffffffu, ml0, off));
            ml1 = fmaxf(ml1, __shfl_xor_sync(0xffffffffu, ml1, off));
        }
        float mn0 = fmaxf(m0, ml0), mn1 = fmaxf(m1, ml1);
        float c0 = __expf(m0 - mn0), c1 = __expf(m1 - mn1);
        float ls0 = 0.f, ls1 = 0.f;
#pragma unroll
        for (int nf = 0; nf < 8; nf++) {
            float p0 = __expf(sacc[nf][0] - mn0);
            float p1 = __expf(sacc[nf][1] - mn0);
            float p2 = __expf(sacc[nf][2] - mn1);
            float p3 = __expf(sacc[nf][3] - mn1);
            ls0 += p0 + p1;
            ls1 += p2 + p3;
            int wp = nf * 4 + lc;     // word index of col pair within row
            p32[r0 * 32 + (wp ^ swq)]       = h2_as_u32(__floats2half2_rn(p0, p1));
            p32[(r0 + 8) * 32 + (wp ^ swq)] = h2_as_u32(__floats2half2_rn(p2, p3));
        }
#pragma unroll
        for (int off = 1; off < 4; off <<= 1) {
            ls0 += __shfl_xor_sync(0xffffffffu, ls0, off);
            ls1 += __shfl_xor_sync(0xffffffffu, ls1, off);
        }
        l0 = l0 * c0 + ls0;
        l1 = l1 * c1 + ls1;
        m0 = mn0; m1 = mn1;
#pragma unroll
        for (int nf = 0; nf < 8; nf++) {
            oacc[nf][0] *= c0;
            oacc[nf][1] *= c0;
            oacc[nf][2] *= c1;
            oacc[nf][3] *= c1;
        }
        __syncwarp();

        // O += P @ V  (A = P from this warp's own rows, B = Vt)
#pragma unroll
        for (int ks = 0; ks < 4; ks++) {
            int p = ks * 8 + lc;
            uint32_t pafr[4];
            pafr[0] = p32[r0 * 32 + (p ^ swq)];
            pafr[1] = p32[(r0 + 8) * 32 + (p ^ swq)];
            pafr[2] = p32[r0 * 32 + ((p + 4) ^ swq)];
            pafr[3] = p32[(r0 + 8) * 32 + ((p + 4) ^ swq)];
#pragma unroll
            for (int nf = 0; nf < 8; nf++) {
                int n0 = nf * 8 + lr;
                int sw = (n0 & 7) << 2;
                uint32_t bfr[2];
                bfr[0] = vsm[n0 * 32 + (p ^ sw)];
                bfr[1] = vsm[n0 * 32 + ((p + 4) ^ sw)];
                mma_f16(oacc[nf], pafr, bfr);
            }
        }
        __syncthreads();
    }

    // write y (fp16)
    float inv0 = 1.0f / l0, inv1 = 1.0f / l1;
#pragma unroll
    for (int nf = 0; nf < 8; nf++) {
        int gc = h * HD_ + nf * 8 + 2 * lc;
        size_t o0 = (size_t)(b * T_ + rg0) * C_ + gc;
        size_t o1 = (size_t)(b * T_ + rg0 + 8) * C_ + gc;
        *(__half2*)(y + o0) = __floats2half2_rn(oacc[nf][0] * inv0, oacc[nf][1] * inv0);
        *(__half2*)(y + o1) = __floats2half2_rn(oacc[nf][2] * inv1, oacc[nf][3] * inv1);
    }
}

// ---------------------------------------------------------------------------
// Launch
// ---------------------------------------------------------------------------
extern "C" void kernel_launch(void* const* d_in, const int* in_sizes, int n_in,
                              void* d_out, int out_size) {
    const float* x       = (const float*)d_in[0];
    const float* ln1_g   = (const float*)d_in[1];
    const float* ln1_b   = (const float*)d_in[2];
    const float* W_qkv   = (const float*)d_in[3];
    const float* W_attn  = (const float*)d_in[4];
    const float* ln2_g   = (const float*)d_in[5];
    const float* ln2_b   = (const float*)d_in[6];
    const float* W_fc    = (const float*)d_in[7];
    const float* W_mlp   = (const float*)d_in[8];
    float* out = (float*)d_out;

    __half *ln, *qkv, *vtb, *yb, *hb, *wq, *wa, *wf, *wm;
    float* x1;
    cudaGetSymbolAddress((void**)&ln, g_ln);
    cudaGetSymbolAddress((void**)&qkv, g_qkv);
    cudaGetSymbolAddress((void**)&vtb, g_vt);
    cudaGetSymbolAddress((void**)&yb, g_y);
    cudaGetSymbolAddress((void**)&x1, g_x1);
    cudaGetSymbolAddress((void**)&hb, g_h);
    cudaGetSymbolAddress((void**)&wq, g_wq);
    cudaGetSymbolAddress((void**)&wa, g_wa);
    cudaGetSymbolAddress((void**)&wf, g_wf);
    cudaGetSymbolAddress((void**)&wm, g_wm);

    cudaFuncSetAttribute((tc_gemm<0, 128>), cudaFuncAttributeMaxDynamicSharedMemorySize, GemmCfg<128>::SMEM);
    cudaFuncSetAttribute((tc_gemm<2, 128>), cudaFuncAttributeMaxDynamicSharedMemorySize, GemmCfg<128>::SMEM);
    cudaFuncSetAttribute((tc_gemm<1, 64>),  cudaFuncAttributeMaxDynamicSharedMemorySize, GemmCfg<64>::SMEM);
    cudaFuncSetAttribute(attn_tc, cudaFuncAttributeMaxDynamicSharedMemorySize, ATTN_SMEM);

    // 0) weights -> fp16 [N,K], single launch
    wconv_all<<<WT_TOT, dim3(32, 8)>>>(W_qkv, W_attn, W_fc, W_mlp, wq, wa, wf, wm);

    // 1) LN1 -> fp16
    ln_kernel<<<BT_ / 8, 256>>>(x, ln1_g, ln1_b, ln);
    // 2) QKV = ln1 @ W_qkv -> fp16
    tc_gemm<0, 128><<<dim3(3 * C_ / 128, BT_ / 128), 256, GemmCfg<128>::SMEM>>>(
        ln, wq, nullptr, qkv, BT_, 3 * C_, C_);
    // 3) V transpose (fp16)
    vt_kernel<<<dim3(T_ / 32, B_ * H_ * 2), dim3(32, 8)>>>(qkv, vtb);
    // 4) causal flash attention (fp16 mma)
    attn_tc<<<dim3(T_ / 64, B_ * H_), 128, ATTN_SMEM>>>(qkv, vtb, yb);
    // 5) x1 = x + y @ W_attn_proj (fp32 out), BN=64 for wave balance
    tc_gemm<1, 64><<<dim3(C_ / 64, BT_ / 128), 256, GemmCfg<64>::SMEM>>>(
        yb, wa, x, x1, BT_, C_, C_);
    // 6) LN2 -> fp16
    ln_kernel<<<BT_ / 8, 256>>>(x1, ln2_g, ln2_b, ln);
    // 7) h = gelu(ln2 @ W_fc) -> fp16
    tc_gemm<2, 128><<<dim3(4 * C_ / 128, BT_ / 128), 256, GemmCfg<128>::SMEM>>>(
        ln, wf, nullptr, hb, BT_, 4 * C_, C_);
    // 8) out = x1 + h @ W_mlp_proj (fp32 out), BN=64
    tc_gemm<1, 64><<<dim3(C_ / 64, BT_ / 128), 256, GemmCfg<64>::SMEM>>>(
        hb, wm, x1, out, BT_, C_, 4 * C_);
}

// round 13
// speedup vs baseline: 1.8998x; 1.0801x over previous
#include <cuda_runtime.h>
#include <cuda_fp16.h>
#include <math.h>
#include <stdint.h>

// Problem constants
#define B_ 2
#define T_ 2048
#define C_ 768
#define H_ 12
#define HD_ 64
#define BT_ (B_ * T_)   // 4096

// ---------------------------------------------------------------------------
// Scratch (device globals; no allocation allowed)
// ---------------------------------------------------------------------------
__device__ __half g_ln[BT_ * C_];            // LN output (fp16)
__device__ __half g_qkv[BT_ * 3 * C_];       // QKV (fp16)
__device__ __half g_y[BT_ * C_];             // attention output (fp16)
__device__ float  g_x1[BT_ * C_];            // x + attn (fp32)
__device__ __half g_h[BT_ * 4 * C_];         // gelu(fc) (fp16)
// fp16 transposed weights [N,K]
__device__ __half g_wq[3 * C_ * C_];
__device__ __half g_wa[C_ * C_];
__device__ __half g_wf[4 * C_ * C_];
__device__ __half g_wm[C_ * 4 * C_];

// ---------------------------------------------------------------------------
// Helpers
// ---------------------------------------------------------------------------
__device__ __forceinline__ uint32_t smem_u32(const void* p) {
    uint32_t a;
    asm("{ .reg .u64 t; cvta.to.shared.u64 t, %1; cvt.u32.u64 %0, t; }"
        : "=r"(a) : "l"(p));
    return a;
}

__device__ __forceinline__ uint32_t h2_as_u32(__half2 h) {
    union { __half2 h2; uint32_t u; } cvt;
    cvt.h2 = h;
    return cvt.u;
}

#define CP_ASYNC16(dst, src) \
    asm volatile("cp.async.cg.shared.global [%0], [%1], 16;" :: "r"(dst), "l"(src))
#define CP_COMMIT() asm volatile("cp.async.commit_group;" ::: "memory")
#define CP_WAIT(n)  asm volatile("cp.async.wait_group %0;" :: "n"(n) : "memory")

// m16n8k16 f16 inputs, f32 accumulate
__device__ __forceinline__ void mma_f16(float* d, const uint32_t* a, const uint32_t* b) {
    asm volatile(
        "mma.sync.aligned.m16n8k16.row.col.f32.f16.f16.f32 "
        "{%0,%1,%2,%3}, {%4,%5,%6,%7}, {%8,%9}, {%0,%1,%2,%3};"
        : "+f"(d[0]), "+f"(d[1]), "+f"(d[2]), "+f"(d[3])
        : "r"(a[0]), "r"(a[1]), "r"(a[2]), "r"(a[3]), "r"(b[0]), "r"(b[1]));
}

__device__ __forceinline__ void ldsm_x4(uint32_t* r, uint32_t a) {
    asm volatile("ldmatrix.sync.aligned.m8n8.x4.shared.b16 {%0,%1,%2,%3}, [%4];"
        : "=r"(r[0]), "=r"(r[1]), "=r"(r[2]), "=r"(r[3]) : "r"(a));
}
__device__ __forceinline__ void ldsm_x4_t(uint32_t* r, uint32_t a) {
    asm volatile("ldmatrix.sync.aligned.m8n8.x4.trans.shared.b16 {%0,%1,%2,%3}, [%4];"
        : "=r"(r[0]), "=r"(r[1]), "=r"(r[2]), "=r"(r[3]) : "r"(a));
}

// ---------------------------------------------------------------------------
// Fused weight transpose+convert (all four weights, one launch).
// ---------------------------------------------------------------------------
#define WT_QKV 1728
#define WT_A   576
#define WT_FC  2304
#define WT_MLP 2304
#define WT_TOT (WT_QKV + WT_A + WT_FC + WT_MLP)

__global__ void wconv_all(const float* __restrict__ iq, const float* __restrict__ ia,
                          const float* __restrict__ ifc, const float* __restrict__ im,
                          __half* __restrict__ oq, __half* __restrict__ oa,
                          __half* __restrict__ ofc, __half* __restrict__ om) {
    __shared__ float tile[32][33];
    int t = blockIdx.x;
    const float* in;
    __half* out;
    int K, N;
    if (t < WT_QKV) { in = iq; out = oq; K = C_; N = 3 * C_; }
    else if (t < WT_QKV + WT_A) { t -= WT_QKV; in = ia; out = oa; K = C_; N = C_; }
    else if (t < WT_QKV + WT_A + WT_FC) { t -= WT_QKV + WT_A; in = ifc; out = ofc; K = C_; N = 4 * C_; }
    else { t -= WT_QKV + WT_A + WT_FC; in = im; out = om; K = 4 * C_; N = C_; }
    int tiles_n = N >> 5;
    int n0 = (t % tiles_n) << 5, k0 = (t / tiles_n) << 5;
#pragma unroll
    for (int i = threadIdx.y; i < 32; i += 8)
        tile[i][threadIdx.x] = in[(size_t)(k0 + i) * N + n0 + threadIdx.x];
    __syncthreads();
#pragma unroll
    for (int i = threadIdx.y; i < 32; i += 8)
        out[(size_t)(n0 + i) * K + k0 + threadIdx.x] = __float2half_rn(tile[threadIdx.x][i]);
}

// ---------------------------------------------------------------------------
// LayerNorm: warp per row, float4, warp-only reduction. Output fp16.
// ---------------------------------------------------------------------------
__global__ void ln_kernel(const float* __restrict__ x, const float* __restrict__ g,
                          const float* __restrict__ b, __half* __restrict__ out) {
    int row = blockIdx.x * 8 + (threadIdx.x >> 5);
    int lane = threadIdx.x & 31;
    const float4* xr = (const float4*)(x + (size_t)row * C_);
    float4 v[6];
    float s = 0.f, sq = 0.f;
#pragma unroll
    for (int i = 0; i < 6; i++) {
        v[i] = xr[lane + i * 32];
        s  += v[i].x + v[i].y + v[i].z + v[i].w;
        sq += v[i].x * v[i].x + v[i].y * v[i].y + v[i].z * v[i].z + v[i].w * v[i].w;
    }
#pragma unroll
    for (int off = 16; off; off >>= 1) {
        s  += __shfl_xor_sync(0xffffffffu, s, off);
        sq += __shfl_xor_sync(0xffffffffu, sq, off);
    }
    float mean = s * (1.0f / C_);
    float var  = sq * (1.0f / C_) - mean * mean;
    float rstd = rsqrtf(var + 1e-5f);
    const float4* g4 = (const float4*)g;
    const float4* b4 = (const float4*)b;
    uint2* o8 = (uint2*)(out + (size_t)row * C_);
#pragma unroll
    for (int i = 0; i < 6; i++) {
        int idx = lane + i * 32;
        float4 gv = g4[idx], bv = b4[idx];
        float r0 = (v[i].x - mean) * rstd * gv.x + bv.x;
        float r1 = (v[i].y - mean) * rstd * gv.y + bv.y;
        float r2 = (v[i].z - mean) * rstd * gv.z + bv.z;
        float r3 = (v[i].w - mean) * rstd * gv.w + bv.w;
        uint2 u;
        u.x = h2_as_u32(__floats2half2_rn(r0, r1));
        u.y = h2_as_u32(__floats2half2_rn(r2, r3));
        o8[idx] = u;
    }
}

// ---------------------------------------------------------------------------
// f16 GEMM: C[M,N] = A[M,K] @ Wt[N,K]^T, fp16 in, fp32 accumulate.
// BM=128, BN template (128 or 64), BK=64, 3-stage cp.async, 256 threads.
// Fragment loads via ldmatrix.x4.
// EPI: 0 = half out, 1 = float out += res, 2 = GELU -> half out
// ---------------------------------------------------------------------------
#define A_STAGE_BYTES 16384
template <int BN> struct GemmCfg {
    static const int B_STAGE_BYTES = BN * 128;
    static const int STAGE_BYTES = A_STAGE_BYTES + B_STAGE_BYTES;
    static const int SMEM = 3 * STAGE_BYTES;
    static const int MT = (BN == 128) ? 4 : 2;
};

template <int BN>
__device__ __forceinline__ void load_stage(uint32_t sa, uint32_t sb,
                                           const __half* __restrict__ Ab,
                                           const __half* __restrict__ Wb,
                                           int K, int kb, int tid) {
    int k0 = kb * 64;
#pragma unroll
    for (int t = 0; t < 4; t++) {
        int linear = tid + t * 256;
        int m = linear >> 3, c = linear & 7;
        uint32_t sw = (uint32_t)((m * 32 + ((c * 4) ^ ((m & 7) << 2))) * 4);
        CP_ASYNC16(sa + sw, Ab + (size_t)m * K + k0 + c * 8);
    }
#pragma unroll
    for (int t = 0; t < BN / 32; t++) {
        int linear = tid + t * 256;
        int m = linear >> 3, c = linear & 7;
        uint32_t sw = (uint32_t)((m * 32 + ((c * 4) ^ ((m & 7) << 2))) * 4);
        CP_ASYNC16(sb + sw, Wb + (size_t)m * K + k0 + c * 8);
    }
}

template <int EPI, int BN>
__global__ __launch_bounds__(256, 2)
void tc_gemm(const __half* __restrict__ A, const __half* __restrict__ Wt,
             const float* __restrict__ res, void* __restrict__ Cm,
             int M, int N, int K) {
    typedef GemmCfg<BN> CFG;
    const int MT = CFG::MT;
    extern __shared__ __align__(16) char dsm[];
    uint32_t sbase = smem_u32(dsm);

    int tid = threadIdx.x;
    int wid = tid >> 5, lane = tid & 31;
    int warp_m, warp_n;
    if (BN == 128) { warp_m = wid >> 2; warp_n = wid & 3; }
    else           { warp_m = wid >> 1; warp_n = wid & 1; }
    int lr = lane >> 2, lc = lane & 3;
    const int KB = K >> 6;

    // ldmatrix per-thread addressing (constant parts)
    int swl = (lane & 7) << 2;                         // word swizzle
    int arow = warp_m * (MT * 16) + (lane & 15);       // + mt*16
    uint32_t ahi4 = (uint32_t)((lane >> 4) * 4);
    int brow = warp_n * 32 + ((lane >> 4) << 3) + (lane & 7);   // + ntp*16
    uint32_t bhi4 = (uint32_t)(((lane >> 3) & 1) * 4);

    const __half* Ab = A + (size_t)blockIdx.y * 128 * K;
    const __half* Wb = Wt + (size_t)blockIdx.x * BN * K;

    float acc[CFG::MT][4][4];
#pragma unroll
    for (int i = 0; i < MT; i++)
#pragma unroll
        for (int j = 0; j < 4; j++)
#pragma unroll
            for (int r = 0; r < 4; r++) acc[i][j][r] = 0.f;

    load_stage<BN>(sbase, sbase + A_STAGE_BYTES, Ab, Wb, K, 0, tid);
    CP_COMMIT();
    load_stage<BN>(sbase + CFG::STAGE_BYTES, sbase + CFG::STAGE_BYTES + A_STAGE_BYTES,
                   Ab, Wb, K, 1, tid);
    CP_COMMIT();

    for (int kb = 0; kb < KB; kb++) {
        int s = kb % 3;
        if (kb + 1 < KB) { CP_WAIT(1); } else { CP_WAIT(0); }
        __syncthreads();
        if (kb + 2 < KB) {
            int sn = (kb + 2) % 3;
            load_stage<BN>(sbase + sn * CFG::STAGE_BYTES,
                           sbase + sn * CFG::STAGE_BYTES + A_STAGE_BYTES,
                           Ab, Wb, K, kb + 2, tid);
            CP_COMMIT();
        }

        uint32_t as_addr = sbase + s * CFG::STAGE_BYTES;
        uint32_t bs_addr = as_addr + A_STAGE_BYTES;
#pragma unroll
        for (int ks = 0; ks < 4; ks++) {
            uint32_t wa = (uint32_t)(((ks * 8 + ahi4) ^ swl) * 4);
            uint32_t wb = (uint32_t)(((ks * 8 + bhi4) ^ swl) * 4);
            uint32_t afr[CFG::MT][4], bfr[2][4];
#pragma unroll
            for (int mt = 0; mt < MT; mt++)
                ldsm_x4(afr[mt], as_addr + (uint32_t)(arow + mt * 16) * 128 + wa);
#pragma unroll
            for (int ntp = 0; ntp < 2; ntp++)
                ldsm_x4(bfr[ntp], bs_addr + (uint32_t)(brow + ntp * 16) * 128 + wb);
#pragma unroll
            for (int mt = 0; mt < MT; mt++)
#pragma unroll
                for (int nt = 0; nt < 4; nt++)
                    mma_f16(acc[mt][nt], afr[mt], bfr[nt >> 1] + 2 * (nt & 1));
        }
    }

    __syncthreads();
    int gm0 = blockIdx.y * 128 + warp_m * (MT * 16);
    int gn0 = blockIdx.x * BN + warp_n * 32;
#pragma unroll
    for (int mt = 0; mt < MT; mt++) {
#pragma unroll
        for (int nt = 0; nt < 4; nt++) {
            int gm = gm0 + mt * 16 + lr;
            int gn = gn0 + nt * 8 + lc * 2;
#pragma unroll
            for (int half_ = 0; half_ < 2; half_++) {
                int row = gm + half_ * 8;
                size_t off = (size_t)row * N + gn;
                float vx = acc[mt][nt][half_ * 2 + 0];
                float vy = acc[mt][nt][half_ * 2 + 1];
                if (EPI == 1) {
                    float2 rs = *(const float2*)(res + off);
                    float2 v = make_float2(vx + rs.x, vy + rs.y);
                    *(float2*)((float*)Cm + off) = v;
                } else if (EPI == 2) {
                    vx = 0.5f * vx * (1.0f + erff(vx * 0.7071067811865475f));
                    vy = 0.5f * vy * (1.0f + erff(vy * 0.7071067811865475f));
                    *(__half2*)((__half*)Cm + off) = __floats2half2_rn(vx, vy);
                } else {
                    *(__half2*)((__half*)Cm + off) = __floats2half2_rn(vx, vy);
                }
            }
        }
    }
}

// ---------------------------------------------------------------------------
// Tensor-core flash attention (fp16 in / fp32 accum, causal).
// Grid: (T/64, B*H), 128 threads. V loaded t-major from qkv; PV B-fragments
// via ldmatrix.trans (no V pre-transpose needed).
// smem halfs: Q [0,4096) | P [4096,8192) | K[2] [8192,16384) | V[2] [16384,24576)
// ---------------------------------------------------------------------------
#define ATTN_SMEM (24576 * 2)   // 48KB

__device__ __forceinline__ void attn_load_kv(uint32_t sb, const __half* __restrict__ kbase,
                                             const __half* __restrict__ vbase,
                                             int j, int s, int tid) {
    uint32_t kdst = sb + (uint32_t)(8192 + s * 4096) * 2;
    uint32_t vdst = sb + (uint32_t)(16384 + s * 4096) * 2;
#pragma unroll
    for (int t = 0; t < 4; t++) {
        int linear = tid + t * 128;
        int r = linear >> 3, c = linear & 7;
        uint32_t sw = (uint32_t)((r * 32 + ((c * 4) ^ ((r & 7) << 2))) * 4);
        size_t go = (size_t)(j * 64 + r) * 3 * C_ + c * 8;
        CP_ASYNC16(kdst + sw, kbase + go);
        CP_ASYNC16(vdst + sw, vbase + go);
    }
}

__global__ __launch_bounds__(128, 2)
void attn_tc(const __half* __restrict__ qkv, __half* __restrict__ y) {
    extern __shared__ __align__(16) char smc[];
    uint32_t sb = smem_u32(smc);

    int qb = gridDim.x - 1 - blockIdx.x;  // longest blocks first
    int bh = blockIdx.y;
    int b = bh / H_, h = bh % H_;
    int tid = threadIdx.x, wid = tid >> 5, lane = tid & 31;
    int lr = lane >> 2, lc = lane & 3;

    const __half* qbase = qkv + (size_t)b * T_ * 3 * C_ + h * HD_;
    const __half* kbase = qbase + C_;
    const __half* vbase = qbase + 2 * C_;

    // load Q tile
#pragma unroll
    for (int t = 0; t < 4; t++) {
        int linear = tid + t * 128;
        int r = linear >> 3, c = linear & 7;
        uint32_t sw = (uint32_t)((r * 32 + ((c * 4) ^ ((r & 7) << 2))) * 4);
        CP_ASYNC16(sb + sw, qbase + (size_t)(qb * 64 + r) * 3 * C_ + c * 8);
    }
    CP_COMMIT();
    attn_load_kv(sb, kbase, vbase, 0, 0, tid);
    CP_COMMIT();

    CP_WAIT(1);
    __syncthreads();

    // ldmatrix constants
    int swl = (lane & 7) << 2;
    int arow = wid * 16 + (lane & 15);                       // A-type rows (Q, P)
    uint32_t ahi4 = (uint32_t)((lane >> 4) * 4);
    int brow = ((lane >> 4) << 3) + (lane & 7);              // B-type rows (K) + ntp*16
    uint32_t bhi4 = (uint32_t)(((lane >> 3) & 1) * 4);
    int vtloc = (((lane >> 3) & 1) << 3) + (lane & 7);       // V trans t-row + ks*16
    uint32_t vdc = (uint32_t)(lane >> 4);                    // V d-chunk + 2*nfp

    // Q fragments
    uint32_t qfr[4][4];
#pragma unroll
    for (int ks = 0; ks < 4; ks++) {
        uint32_t w = (uint32_t)(((ks * 8 + ahi4) ^ swl) * 4);
        ldsm_x4(qfr[ks], sb + (uint32_t)arow * 128 + w);
    }

    float oacc[8][4];
#pragma unroll
    for (int i = 0; i < 8; i++)
#pragma unroll
        for (int e = 0; e < 4; e++) oacc[i][e] = 0.f;
    float m0 = -1e30f, m1 = -1e30f, l0 = 0.f, l1 = 0.f;

    int r0 = wid * 16 + lr;
    int rg0 = qb * 64 + r0;
    uint32_t psm = sb + 4096 * 2;         // P region
    uint32_t* p32 = (uint32_t*)(smc) + 2048;

    for (int j = 0; j <= qb; j++) {
        int s = j & 1;
        if (j < qb) {
            attn_load_kv(sb, kbase, vbase, j + 1, s ^ 1, tid);
            CP_COMMIT();
            CP_WAIT(1);
        } else {
            CP_WAIT(0);
        }
        __syncthreads();

        uint32_t ksm = sb + (uint32_t)(8192 + s * 4096) * 2;
        uint32_t vsm = sb + (uint32_t)(16384 + s * 4096) * 2;

        // S = Q @ K^T
        float sacc[8][4];
#pragma unroll
        for (int nf = 0; nf < 8; nf++)
#pragma unroll
            for (int e = 0; e < 4; e++) sacc[nf][e] = 0.f;
#pragma unroll
        for (int ks = 0; ks < 4; ks++) {
            uint32_t wb = (uint32_t)(((ks * 8 + bhi4) ^ swl) * 4);
#pragma unroll
            for (int ntp = 0; ntp < 4; ntp++) {
                uint32_t kf[4];
                ldsm_x4(kf, ksm + (uint32_t)(brow + ntp * 16) * 128 + wb);
                mma_f16(sacc[2 * ntp],     qfr[ks], kf);
                mma_f16(sacc[2 * ntp + 1], qfr[ks], kf + 2);
            }
        }

        // scale + causal mask (diagonal tile only)
#pragma unroll
        for (int nf = 0; nf < 8; nf++) {
#pragma unroll
            for (int e = 0; e < 4; e++) {
                float v = sacc[nf][e] * 0.125f;
                if (j == qb) {
                    int col = j * 64 + nf * 8 + 2 * lc + (e & 1);
                    int row = (e < 2) ? rg0 : rg0 + 8;
                    if (col > row) v = -1e30f;
                }
                sacc[nf][e] = v;
            }
        }

        // online softmax
        float ml0 = -1e30f, ml1 = -1e30f;
#pragma unroll
        for (int nf = 0; nf < 8; nf++) {
            ml0 = fmaxf(ml0, fmaxf(sacc[nf][0], sacc[nf][1]));
            ml1 = fmaxf(ml1, fmaxf(sacc[nf][2], sacc[nf][3]));
        }
#pragma unroll
        for (int off = 1; off < 4; off <<= 1) {
            ml0 = fmaxf(ml0, __shfl_xor_sync(0xffffffffu, ml0, off));
            ml1 = fmaxf(ml1, __shfl_xor_sync(0xffffffffu, ml1, off));
        }
        float mn0 = fmaxf(m0, ml0), mn1 = fmaxf(m1, ml1);
        float c0 = __expf(m0 - mn0), c1 = __expf(m1 - mn1);
        float ls0 = 0.f, ls1 = 0.f;
        int swq = (r0 & 7) << 2;
#pragma unroll
        for (int nf = 0; nf < 8; nf++) {
            float p0 = __expf(sacc[nf][0] - mn0);
            float p1 = __expf(sacc[nf][1] - mn0);
            float p2 = __expf(sacc[nf][2] - mn1);
            float p3 = __expf(sacc[nf][3] - mn1);
            ls0 += p0 + p1;
            ls1 += p2 + p3;
            int wp = nf * 4 + lc;
            p32[r0 * 32 + (wp ^ swq)]       = h2_as_u32(__floats2half2_rn(p0, p1));
            p32[(r0 + 8) * 32 + (wp ^ swq)] = h2_as_u32(__floats2half2_rn(p2, p3));
        }
#pragma unroll
        for (int off = 1; off < 4; off <<= 1) {
            ls0 += __shfl_xor_sync(0xffffffffu, ls0, off);
            ls1 += __shfl_xor_sync(0xffffffffu, ls1, off);
        }
        l0 = l0 * c0 + ls0;
        l1 = l1 * c1 + ls1;
        m0 = mn0; m1 = mn1;
#pragma unroll
        for (int nf = 0; nf < 8; nf++) {
            oacc[nf][0] *= c0;
            oacc[nf][1] *= c0;
            oacc[nf][2] *= c1;
            oacc[nf][3] *= c1;
        }
        __syncwarp();

        // O += P @ V  (P via ldsm, V via ldsm.trans from t-major tile)
#pragma unroll
        for (int ks = 0; ks < 4; ks++) {
            uint32_t pafr[4];
            uint32_t wp = (uint32_t)(((ks * 8 + ahi4) ^ swl) * 4);
            ldsm_x4(pafr, psm + (uint32_t)arow * 128 + wp);
            int trow = ks * 16 + vtloc;
            uint32_t vbaseaddr = vsm + (uint32_t)trow * 128;
            uint32_t vswl = (uint32_t)((trow & 7) << 2);
#pragma unroll
            for (int nfp = 0; nfp < 4; nfp++) {
                uint32_t vf[4];
                uint32_t wv = (uint32_t)((((2 * nfp + vdc) * 4) ^ vswl) * 4);
                ldsm_x4_t(vf, vbaseaddr + wv);
                mma_f16(oacc[2 * nfp],     pafr, vf);
                mma_f16(oacc[2 * nfp + 1], pafr, vf + 2);
            }
        }
        __syncthreads();
    }

    // write y (fp16)
    float inv0 = 1.0f / l0, inv1 = 1.0f / l1;
#pragma unroll
    for (int nf = 0; nf < 8; nf++) {
        int gc = h * HD_ + nf * 8 + 2 * lc;
        size_t o0 = (size_t)(b * T_ + rg0) * C_ + gc;
        size_t o1 = (size_t)(b * T_ + rg0 + 8) * C_ + gc;
        *(__half2*)(y + o0) = __floats2half2_rn(oacc[nf][0] * inv0, oacc[nf][1] * inv0);
        *(__half2*)(y + o1) = __floats2half2_rn(oacc[nf][2] * inv1, oacc[nf][3] * inv1);
    }
}

// ---------------------------------------------------------------------------
// Launch
// ---------------------------------------------------------------------------
extern "C" void kernel_launch(void* const* d_in, const int* in_sizes, int n_in,
                              void* d_out, int out_size) {
    const float* x       = (const float*)d_in[0];
    const float* ln1_g   = (const float*)d_in[1];
    const float* ln1_b   = (const float*)d_in[2];
    const float* W_qkv   = (const float*)d_in[3];
    const float* W_attn  = (const float*)d_in[4];
    const float* ln2_g   = (const float*)d_in[5];
    const float* ln2_b   = (const float*)d_in[6];
    const float* W_fc    = (const float*)d_in[7];
    const float* W_mlp   = (const float*)d_in[8];
    float* out = (float*)d_out;

    __half *ln, *qkv, *yb, *hb, *wq, *wa, *wf, *wm;
    float* x1;
    cudaGetSymbolAddress((void**)&ln, g_ln);
    cudaGetSymbolAddress((void**)&qkv, g_qkv);
    cudaGetSymbolAddress((void**)&yb, g_y);
    cudaGetSymbolAddress((void**)&x1, g_x1);
    cudaGetSymbolAddress((void**)&hb, g_h);
    cudaGetSymbolAddress((void**)&wq, g_wq);
    cudaGetSymbolAddress((void**)&wa, g_wa);
    cudaGetSymbolAddress((void**)&wf, g_wf);
    cudaGetSymbolAddress((void**)&wm, g_wm);

    cudaFuncSetAttribute((tc_gemm<0, 128>), cudaFuncAttributeMaxDynamicSharedMemorySize, GemmCfg<128>::SMEM);
    cudaFuncSetAttribute((tc_gemm<2, 128>), cudaFuncAttributeMaxDynamicSharedMemorySize, GemmCfg<128>::SMEM);
    cudaFuncSetAttribute((tc_gemm<1, 64>),  cudaFuncAttributeMaxDynamicSharedMemorySize, GemmCfg<64>::SMEM);
    cudaFuncSetAttribute(attn_tc, cudaFuncAttributeMaxDynamicSharedMemorySize, ATTN_SMEM);

    // 0) weights -> fp16 [N,K], single launch
    wconv_all<<<WT_TOT, dim3(32, 8)>>>(W_qkv, W_attn, W_fc, W_mlp, wq, wa, wf, wm);

    // 1) LN1 -> fp16
    ln_kernel<<<BT_ / 8, 256>>>(x, ln1_g, ln1_b, ln);
    // 2) QKV = ln1 @ W_qkv -> fp16
    tc_gemm<0, 128><<<dim3(3 * C_ / 128, BT_ / 128), 256, GemmCfg<128>::SMEM>>>(
        ln, wq, nullptr, qkv, BT_, 3 * C_, C_);
    // 3) causal flash attention (fp16 mma, ldmatrix)
    attn_tc<<<dim3(T_ / 64, B_ * H_), 128, ATTN_SMEM>>>(qkv, yb);
    // 4) x1 = x + y @ W_attn_proj (fp32 out), BN=64
    tc_gemm<1, 64><<<dim3(C_ / 64, BT_ / 128), 256, GemmCfg<64>::SMEM>>>(
        yb, wa, x, x1, BT_, C_, C_);
    // 5) LN2 -> fp16
    ln_kernel<<<BT_ / 8, 256>>>(x1, ln2_g, ln2_b, ln);
    // 6) h = gelu(ln2 @ W_fc) -> fp16
    tc_gemm<2, 128><<<dim3(4 * C_ / 128, BT_ / 128), 256, GemmCfg<128>::SMEM>>>(
        ln, wf, nullptr, hb, BT_, 4 * C_, C_);
    // 7) out = x1 + h @ W_mlp_proj (fp32 out), BN=64
    tc_gemm<1, 64><<<dim3(C_ / 64, BT_ / 128), 256, GemmCfg<64>::SMEM>>>(
        hb, wm, x1, out, BT_, C_, 4 * C_);
}

// round 14
// speedup vs baseline: 1.9951x; 1.0502x over previous
#include <cuda_runtime.h>
#include <cuda_fp16.h>
#include <math.h>
#include <stdint.h>

// Problem constants
#define B_ 2
#define T_ 2048
#define C_ 768
#define H_ 12
#define HD_ 64
#define BT_ (B_ * T_)   // 4096

// ---------------------------------------------------------------------------
// Scratch (device globals; no allocation allowed)
// ---------------------------------------------------------------------------
__device__ __half g_ln[BT_ * C_];            // LN output (fp16)
__device__ __half g_qkv[BT_ * 3 * C_];       // QKV (fp16)
__device__ __half g_y[BT_ * C_];             // attention output (fp16)
__device__ float  g_x1[BT_ * C_];            // x + attn (fp32)
__device__ __half g_h[BT_ * 4 * C_];         // gelu(fc) (fp16)
// fp16 transposed weights [N,K]
__device__ __half g_wq[3 * C_ * C_];
__device__ __half g_wa[C_ * C_];
__device__ __half g_wf[4 * C_ * C_];
__device__ __half g_wm[C_ * 4 * C_];

// ---------------------------------------------------------------------------
// Helpers
// ---------------------------------------------------------------------------
__device__ __forceinline__ uint32_t smem_u32(const void* p) {
    uint32_t a;
    asm("{ .reg .u64 t; cvta.to.shared.u64 t, %1; cvt.u32.u64 %0, t; }"
        : "=r"(a) : "l"(p));
    return a;
}

__device__ __forceinline__ uint32_t h2_as_u32(__half2 h) {
    union { __half2 h2; uint32_t u; } cvt;
    cvt.h2 = h;
    return cvt.u;
}

#define CP_ASYNC16(dst, src) \
    asm volatile("cp.async.cg.shared.global [%0], [%1], 16;" :: "r"(dst), "l"(src))
#define CP_COMMIT() asm volatile("cp.async.commit_group;" ::: "memory")
#define CP_WAIT(n)  asm volatile("cp.async.wait_group %0;" :: "n"(n) : "memory")

// m16n8k16 f16 inputs, f32 accumulate
__device__ __forceinline__ void mma_f16(float* d, const uint32_t* a, const uint32_t* b) {
    asm volatile(
        "mma.sync.aligned.m16n8k16.row.col.f32.f16.f16.f32 "
        "{%0,%1,%2,%3}, {%4,%5,%6,%7}, {%8,%9}, {%0,%1,%2,%3};"
        : "+f"(d[0]), "+f"(d[1]), "+f"(d[2]), "+f"(d[3])
        : "r"(a[0]), "r"(a[1]), "r"(a[2]), "r"(a[3]), "r"(b[0]), "r"(b[1]));
}

__device__ __forceinline__ void ldsm_x4(uint32_t* r, uint32_t a) {
    asm volatile("ldmatrix.sync.aligned.m8n8.x4.shared.b16 {%0,%1,%2,%3}, [%4];"
        : "=r"(r[0]), "=r"(r[1]), "=r"(r[2]), "=r"(r[3]) : "r"(a));
}
__device__ __forceinline__ void ldsm_x4_t(uint32_t* r, uint32_t a) {
    asm volatile("ldmatrix.sync.aligned.m8n8.x4.trans.shared.b16 {%0,%1,%2,%3}, [%4];"
        : "=r"(r[0]), "=r"(r[1]), "=r"(r[2]), "=r"(r[3]) : "r"(a));
}

// ---------------------------------------------------------------------------
// Fused weight transpose+convert (all four weights, one launch).
// ---------------------------------------------------------------------------
#define WT_QKV 1728
#define WT_A   576
#define WT_FC  2304
#define WT_MLP 2304
#define WT_TOT (WT_QKV + WT_A + WT_FC + WT_MLP)

__global__ void wconv_all(const float* __restrict__ iq, const float* __restrict__ ia,
                          const float* __restrict__ ifc, const float* __restrict__ im,
                          __half* __restrict__ oq, __half* __restrict__ oa,
                          __half* __restrict__ ofc, __half* __restrict__ om) {
    __shared__ float tile[32][33];
    int t = blockIdx.x;
    const float* in;
    __half* out;
    int K, N;
    if (t < WT_QKV) { in = iq; out = oq; K = C_; N = 3 * C_; }
    else if (t < WT_QKV + WT_A) { t -= WT_QKV; in = ia; out = oa; K = C_; N = C_; }
    else if (t < WT_QKV + WT_A + WT_FC) { t -= WT_QKV + WT_A; in = ifc; out = ofc; K = C_; N = 4 * C_; }
    else { t -= WT_QKV + WT_A + WT_FC; in = im; out = om; K = 4 * C_; N = C_; }
    int tiles_n = N >> 5;
    int n0 = (t % tiles_n) << 5, k0 = (t / tiles_n) << 5;
#pragma unroll
    for (int i = threadIdx.y; i < 32; i += 8)
        tile[i][threadIdx.x] = in[(size_t)(k0 + i) * N + n0 + threadIdx.x];
    __syncthreads();
#pragma unroll
    for (int i = threadIdx.y; i < 32; i += 8)
        out[(size_t)(n0 + i) * K + k0 + threadIdx.x] = __float2half_rn(tile[threadIdx.x][i]);
}

// ---------------------------------------------------------------------------
// LayerNorm: warp per row, float4, warp-only reduction. Output fp16.
// ---------------------------------------------------------------------------
__global__ void ln_kernel(const float* __restrict__ x, const float* __restrict__ g,
                          const float* __restrict__ b, __half* __restrict__ out) {
    int row = blockIdx.x * 8 + (threadIdx.x >> 5);
    int lane = threadIdx.x & 31;
    const float4* xr = (const float4*)(x + (size_t)row * C_);
    float4 v[6];
    float s = 0.f, sq = 0.f;
#pragma unroll
    for (int i = 0; i < 6; i++) {
        v[i] = xr[lane + i * 32];
        s  += v[i].x + v[i].y + v[i].z + v[i].w;
        sq += v[i].x * v[i].x + v[i].y * v[i].y + v[i].z * v[i].z + v[i].w * v[i].w;
    }
#pragma unroll
    for (int off = 16; off; off >>= 1) {
        s  += __shfl_xor_sync(0xffffffffu, s, off);
        sq += __shfl_xor_sync(0xffffffffu, sq, off);
    }
    float mean = s * (1.0f / C_);
    float var  = sq * (1.0f / C_) - mean * mean;
    float rstd = rsqrtf(var + 1e-5f);
    const float4* g4 = (const float4*)g;
    const float4* b4 = (const float4*)b;
    uint2* o8 = (uint2*)(out + (size_t)row * C_);
#pragma unroll
    for (int i = 0; i < 6; i++) {
        int idx = lane + i * 32;
        float4 gv = g4[idx], bv = b4[idx];
        float r0 = (v[i].x - mean) * rstd * gv.x + bv.x;
        float r1 = (v[i].y - mean) * rstd * gv.y + bv.y;
        float r2 = (v[i].z - mean) * rstd * gv.z + bv.z;
        float r3 = (v[i].w - mean) * rstd * gv.w + bv.w;
        uint2 u;
        u.x = h2_as_u32(__floats2half2_rn(r0, r1));
        u.y = h2_as_u32(__floats2half2_rn(r2, r3));
        o8[idx] = u;
    }
}

// ---------------------------------------------------------------------------
// f16 GEMM: C[M,N] = A[M,K] @ Wt[N,K]^T, fp16 in, fp32 accumulate.
// BM=128, BN template (128/64), BK=64, 3-stage cp.async, 256 threads.
// KB (= K/64) is a template param; unroll-by-3 const-folds stage addressing.
// EPI: 0 = half out, 1 = float out += res, 2 = GELU -> half out
// ---------------------------------------------------------------------------
#define A_STAGE_BYTES 16384
template <int BN> struct GemmCfg {
    static const int B_STAGE_BYTES = BN * 128;
    static const int STAGE_BYTES = A_STAGE_BYTES + B_STAGE_BYTES;
    static const int SMEM = 3 * STAGE_BYTES;
    static const int MT = (BN == 128) ? 4 : 2;
};

template <int BN, int KB>
__device__ __forceinline__ void load_stage(uint32_t sa, uint32_t sb,
                                           const __half* __restrict__ Ab,
                                           const __half* __restrict__ Wb,
                                           int kb, int tid) {
    const int K = KB * 64;
    int k0 = kb * 64;
#pragma unroll
    for (int t = 0; t < 4; t++) {
        int linear = tid + t * 256;
        int m = linear >> 3, c = linear & 7;
        uint32_t sw = (uint32_t)((m * 32 + ((c * 4) ^ ((m & 7) << 2))) * 4);
        CP_ASYNC16(sa + sw, Ab + (size_t)m * K + k0 + c * 8);
    }
#pragma unroll
    for (int t = 0; t < BN / 32; t++) {
        int linear = tid + t * 256;
        int m = linear >> 3, c = linear & 7;
        uint32_t sw = (uint32_t)((m * 32 + ((c * 4) ^ ((m & 7) << 2))) * 4);
        CP_ASYNC16(sb + sw, Wb + (size_t)m * K + k0 + c * 8);
    }
}

template <int EPI, int BN, int KB>
__global__ __launch_bounds__(256, 2)
void tc_gemm(const __half* __restrict__ A, const __half* __restrict__ Wt,
             const float* __restrict__ res, void* __restrict__ Cm,
             int M, int N) {
    typedef GemmCfg<BN> CFG;
    const int MT = CFG::MT;
    const int K = KB * 64;
    extern __shared__ __align__(16) char dsm[];
    uint32_t sbase = smem_u32(dsm);

    int tid = threadIdx.x;
    int wid = tid >> 5, lane = tid & 31;
    int warp_m, warp_n;
    if (BN == 128) { warp_m = wid >> 2; warp_n = wid & 3; }
    else           { warp_m = wid >> 1; warp_n = wid & 1; }
    int lr = lane >> 2, lc = lane & 3;

    // ldmatrix per-thread addressing (constant parts)
    int swl = (lane & 7) << 2;
    int arow = warp_m * (MT * 16) + (lane & 15);
    uint32_t ahi4 = (uint32_t)((lane >> 4) * 4);
    int brow = warp_n * 32 + ((lane >> 4) << 3) + (lane & 7);
    uint32_t bhi4 = (uint32_t)(((lane >> 3) & 1) * 4);

    const __half* Ab = A + (size_t)blockIdx.y * 128 * K;
    const __half* Wb = Wt + (size_t)blockIdx.x * BN * K;

    float acc[CFG::MT][4][4];
#pragma unroll
    for (int i = 0; i < MT; i++)
#pragma unroll
        for (int j = 0; j < 4; j++)
#pragma unroll
            for (int r = 0; r < 4; r++) acc[i][j][r] = 0.f;

    load_stage<BN, KB>(sbase, sbase + A_STAGE_BYTES, Ab, Wb, 0, tid);
    CP_COMMIT();
    load_stage<BN, KB>(sbase + CFG::STAGE_BYTES, sbase + CFG::STAGE_BYTES + A_STAGE_BYTES,
                       Ab, Wb, 1, tid);
    CP_COMMIT();

#pragma unroll 3
    for (int kb = 0; kb < KB; kb++) {
        int s = kb % 3;           // const-folds under unroll 3 (KB % 3 == 0)
        if (kb + 1 < KB) { CP_WAIT(1); } else { CP_WAIT(0); }
        __syncthreads();
        if (kb + 2 < KB) {
            int sn = (kb + 2) % 3;
            load_stage<BN, KB>(sbase + sn * CFG::STAGE_BYTES,
                               sbase + sn * CFG::STAGE_BYTES + A_STAGE_BYTES,
                               Ab, Wb, kb + 2, tid);
            CP_COMMIT();
        }

        uint32_t as_addr = sbase + s * CFG::STAGE_BYTES;
        uint32_t bs_addr = as_addr + A_STAGE_BYTES;
#pragma unroll
        for (int ks = 0; ks < 4; ks++) {
            uint32_t wa = (uint32_t)(((ks * 8 + ahi4) ^ swl) * 4);
            uint32_t wb = (uint32_t)(((ks * 8 + bhi4) ^ swl) * 4);
            uint32_t afr[CFG::MT][4], bfr[2][4];
#pragma unroll
            for (int mt = 0; mt < MT; mt++)
                ldsm_x4(afr[mt], as_addr + (uint32_t)(arow + mt * 16) * 128 + wa);
#pragma unroll
            for (int ntp = 0; ntp < 2; ntp++)
                ldsm_x4(bfr[ntp], bs_addr + (uint32_t)(brow + ntp * 16) * 128 + wb);
#pragma unroll
            for (int mt = 0; mt < MT; mt++)
#pragma unroll
                for (int nt = 0; nt < 4; nt++)
                    mma_f16(acc[mt][nt], afr[mt], bfr[nt >> 1] + 2 * (nt & 1));
        }
    }

    __syncthreads();
    int gm0 = blockIdx.y * 128 + warp_m * (MT * 16);
    int gn0 = blockIdx.x * BN + warp_n * 32;
#pragma unroll
    for (int mt = 0; mt < MT; mt++) {
#pragma unroll
        for (int nt = 0; nt < 4; nt++) {
            int gm = gm0 + mt * 16 + lr;
            int gn = gn0 + nt * 8 + lc * 2;
#pragma unroll
            for (int half_ = 0; half_ < 2; half_++) {
                int row = gm + half_ * 8;
                size_t off = (size_t)row * N + gn;
                float vx = acc[mt][nt][half_ * 2 + 0];
                float vy = acc[mt][nt][half_ * 2 + 1];
                if (EPI == 1) {
                    float2 rs = *(const float2*)(res + off);
                    float2 v = make_float2(vx + rs.x, vy + rs.y);
                    *(float2*)((float*)Cm + off) = v;
                } else if (EPI == 2) {
                    vx = 0.5f * vx * (1.0f + erff(vx * 0.7071067811865475f));
                    vy = 0.5f * vy * (1.0f + erff(vy * 0.7071067811865475f));
                    *(__half2*)((__half*)Cm + off) = __floats2half2_rn(vx, vy);
                } else {
                    *(__half2*)((__half*)Cm + off) = __floats2half2_rn(vx, vy);
                }
            }
        }
    }
}

// ---------------------------------------------------------------------------
// Tensor-core flash attention (fp16 in / fp32 accum, causal).
// Grid: (T/64, B*H), 128 threads, occupancy 3 (forced via launch bounds).
// smem halfs: Q [0,4096) | P [4096,8192) | K[2] [8192,16384) | V[2] [16384,24576)
// ---------------------------------------------------------------------------
#define ATTN_SMEM (24576 * 2)   // 48KB

__device__ __forceinline__ void attn_load_kv(uint32_t sb, const __half* __restrict__ kbase,
                                             const __half* __restrict__ vbase,
                                             int j, int s, int tid) {
    uint32_t kdst = sb + (uint32_t)(8192 + s * 4096) * 2;
    uint32_t vdst = sb + (uint32_t)(16384 + s * 4096) * 2;
#pragma unroll
    for (int t = 0; t < 4; t++) {
        int linear = tid + t * 128;
        int r = linear >> 3, c = linear & 7;
        uint32_t sw = (uint32_t)((r * 32 + ((c * 4) ^ ((r & 7) << 2))) * 4);
        size_t go = (size_t)(j * 64 + r) * 3 * C_ + c * 8;
        CP_ASYNC16(kdst + sw, kbase + go);
        CP_ASYNC16(vdst + sw, vbase + go);
    }
}

__global__ __launch_bounds__(128, 3)
void attn_tc(const __half* __restrict__ qkv, __half* __restrict__ y) {
    extern __shared__ __align__(16) char smc[];
    uint32_t sb = smem_u32(smc);

    int qb = gridDim.x - 1 - blockIdx.x;  // longest blocks first
    int bh = blockIdx.y;
    int b = bh / H_, h = bh % H_;
    int tid = threadIdx.x, wid = tid >> 5, lane = tid & 31;
    int lr = lane >> 2, lc = lane & 3;

    const __half* qbase = qkv + (size_t)b * T_ * 3 * C_ + h * HD_;
    const __half* kbase = qbase + C_;
    const __half* vbase = qbase + 2 * C_;

    // load Q tile
#pragma unroll
    for (int t = 0; t < 4; t++) {
        int linear = tid + t * 128;
        int r = linear >> 3, c = linear & 7;
        uint32_t sw = (uint32_t)((r * 32 + ((c * 4) ^ ((r & 7) << 2))) * 4);
        CP_ASYNC16(sb + sw, qbase + (size_t)(qb * 64 + r) * 3 * C_ + c * 8);
    }
    CP_COMMIT();
    attn_load_kv(sb, kbase, vbase, 0, 0, tid);
    CP_COMMIT();

    CP_WAIT(1);
    __syncthreads();

    // ldmatrix constants
    int swl = (lane & 7) << 2;
    int arow = wid * 16 + (lane & 15);
    uint32_t ahi4 = (uint32_t)((lane >> 4) * 4);
    int brow = ((lane >> 4) << 3) + (lane & 7);
    uint32_t bhi4 = (uint32_t)(((lane >> 3) & 1) * 4);
    int vtloc = (((lane >> 3) & 1) << 3) + (lane & 7);
    uint32_t vdc = (uint32_t)(lane >> 4);

    // Q fragments
    uint32_t qfr[4][4];
#pragma unroll
    for (int ks = 0; ks < 4; ks++) {
        uint32_t w = (uint32_t)(((ks * 8 + ahi4) ^ swl) * 4);
        ldsm_x4(qfr[ks], sb + (uint32_t)arow * 128 + w);
    }

    float oacc[8][4];
#pragma unroll
    for (int i = 0; i < 8; i++)
#pragma unroll
        for (int e = 0; e < 4; e++) oacc[i][e] = 0.f;
    float m0 = -1e30f, m1 = -1e30f, l0 = 0.f, l1 = 0.f;

    int r0 = wid * 16 + lr;
    int rg0 = qb * 64 + r0;
    uint32_t psm = sb + 4096 * 2;
    uint32_t* p32 = (uint32_t*)(smc) + 2048;

    for (int j = 0; j <= qb; j++) {
        int s = j & 1;
        if (j < qb) {
            attn_load_kv(sb, kbase, vbase, j + 1, s ^ 1, tid);
            CP_COMMIT();
            CP_WAIT(1);
        } else {
            CP_WAIT(0);
        }
        __syncthreads();

        uint32_t ksm = sb + (uint32_t)(8192 + s * 4096) * 2;
        uint32_t vsm = sb + (uint32_t)(16384 + s * 4096) * 2;

        // S = Q @ K^T
        float sacc[8][4];
#pragma unroll
        for (int nf = 0; nf < 8; nf++)
#pragma unroll
            for (int e = 0; e < 4; e++) sacc[nf][e] = 0.f;
#pragma unroll
        for (int ks = 0; ks < 4; ks++) {
            uint32_t wb = (uint32_t)(((ks * 8 + bhi4) ^ swl) * 4);
#pragma unroll
            for (int ntp = 0; ntp < 4; ntp++) {
                uint32_t kf[4];
                ldsm_x4(kf, ksm + (uint32_t)(brow + ntp * 16) * 128 + wb);
                mma_f16(sacc[2 * ntp],     qfr[ks], kf);
                mma_f16(sacc[2 * ntp + 1], qfr[ks], kf + 2);
            }
        }

        // scale + causal mask (diagonal tile only)
#pragma unroll
        for (int nf = 0; nf < 8; nf++) {
#pragma unroll
            for (int e = 0; e < 4; e++) {
                float v = sacc[nf][e] * 0.125f;
                if (j == qb) {
                    int col = j * 64 + nf * 8 + 2 * lc + (e & 1);
                    int row = (e < 2) ? rg0 : rg0 + 8;
                    if (col > row) v = -1e30f;
                }
                sacc[nf][e] = v;
            }
        }

        // online softmax
        float ml0 = -1e30f, ml1 = -1e30f;
#pragma unroll
        for (int nf = 0; nf < 8; nf++) {
            ml0 = fmaxf(ml0, fmaxf(sacc[nf][0], sacc[nf][1]));
            ml1 = fmaxf(ml1, fmaxf(sacc[nf][2], sacc[nf][3]));
        }
#pragma unroll
        for (int off = 1; off < 4; off <<= 1) {
            ml0 = fmaxf(ml0, __shfl_xor_sync(0xffffffffu, ml0, off));
            ml1 = fmaxf(ml1, __shfl_xor_sync(0xffffffffu, ml1, off));
        }
        float mn0 = fmaxf(m0, ml0), mn1 = fmaxf(m1, ml1);
        float c0 = __expf(m0 - mn0), c1 = __expf(m1 - mn1);
        float ls0 = 0.f, ls1 = 0.f;
        int swq = (r0 & 7) << 2;
#pragma unroll
        for (int nf = 0; nf < 8; nf++) {
            float p0 = __expf(sacc[nf][0] - mn0);
            float p1 = __expf(sacc[nf][1] - mn0);
            float p2 = __expf(sacc[nf][2] - mn1);
            float p3 = __expf(sacc[nf][3] - mn1);
            ls0 += p0 + p1;
            ls1 += p2 + p3;
            int wp = nf * 4 + lc;
            p32[r0 * 32 + (wp ^ swq)]       = h2_as_u32(__floats2half2_rn(p0, p1));
            p32[(r0 + 8) * 32 + (wp ^ swq)] = h2_as_u32(__floats2half2_rn(p2, p3));
        }
#pragma unroll
        for (int off = 1; off < 4; off <<= 1) {
            ls0 += __shfl_xor_sync(0xffffffffu, ls0, off);
            ls1 += __shfl_xor_sync(0xffffffffu, ls1, off);
        }
        l0 = l0 * c0 + ls0;
        l1 = l1 * c1 + ls1;
        m0 = mn0; m1 = mn1;
#pragma unroll
        for (int nf = 0; nf < 8; nf++) {
            oacc[nf][0] *= c0;
            oacc[nf][1] *= c0;
            oacc[nf][2] *= c1;
            oacc[nf][3] *= c1;
        }
        __syncwarp();

        // O += P @ V  (P via ldsm, V via ldsm.trans from t-major tile)
#pragma unroll
        for (int ks = 0; ks < 4; ks++) {
            uint32_t pafr[4];
            uint32_t wp = (uint32_t)(((ks * 8 + ahi4) ^ swl) * 4);
            ldsm_x4(pafr, psm + (uint32_t)arow * 128 + wp);
            int trow = ks * 16 + vtloc;
            uint32_t vbaseaddr = vsm + (uint32_t)trow * 128;
            uint32_t vswl = (uint32_t)((trow & 7) << 2);
#pragma unroll
            for (int nfp = 0; nfp < 4; nfp++) {
                uint32_t vf[4];
                uint32_t wv = (uint32_t)((((2 * nfp + vdc) * 4) ^ vswl) * 4);
                ldsm_x4_t(vf, vbaseaddr + wv);
                mma_f16(oacc[2 * nfp],     pafr, vf);
                mma_f16(oacc[2 * nfp + 1], pafr, vf + 2);
            }
        }
        __syncthreads();
    }

    // write y (fp16)
    float inv0 = 1.0f / l0, inv1 = 1.0f / l1;
#pragma unroll
    for (int nf = 0; nf < 8; nf++) {
        int gc = h * HD_ + nf * 8 + 2 * lc;
        size_t o0 = (size_t)(b * T_ + rg0) * C_ + gc;
        size_t o1 = (size_t)(b * T_ + rg0 + 8) * C_ + gc;
        *(__half2*)(y + o0) = __floats2half2_rn(oacc[nf][0] * inv0, oacc[nf][1] * inv0);
        *(__half2*)(y + o1) = __floats2half2_rn(oacc[nf][2] * inv1, oacc[nf][3] * inv1);
    }
}

// ---------------------------------------------------------------------------
// Launch
// ---------------------------------------------------------------------------
extern "C" void kernel_launch(void* const* d_in, const int* in_sizes, int n_in,
                              void* d_out, int out_size) {
    const float* x       = (const float*)d_in[0];
    const float* ln1_g   = (const float*)d_in[1];
    const float* ln1_b   = (const float*)d_in[2];
    const float* W_qkv   = (const float*)d_in[3];
    const float* W_attn  = (const float*)d_in[4];
    const float* ln2_g   = (const float*)d_in[5];
    const float* ln2_b   = (const float*)d_in[6];
    const float* W_fc    = (const float*)d_in[7];
    const float* W_mlp   = (const float*)d_in[8];
    float* out = (float*)d_out;

    __half *ln, *qkv, *yb, *hb, *wq, *wa, *wf, *wm;
    float* x1;
    cudaGetSymbolAddress((void**)&ln, g_ln);
    cudaGetSymbolAddress((void**)&qkv, g_qkv);
    cudaGetSymbolAddress((void**)&yb, g_y);
    cudaGetSymbolAddress((void**)&x1, g_x1);
    cudaGetSymbolAddress((void**)&hb, g_h);
    cudaGetSymbolAddress((void**)&wq, g_wq);
    cudaGetSymbolAddress((void**)&wa, g_wa);
    cudaGetSymbolAddress((void**)&wf, g_wf);
    cudaGetSymbolAddress((void**)&wm, g_wm);

    cudaFuncSetAttribute((tc_gemm<0, 128, 12>), cudaFuncAttributeMaxDynamicSharedMemorySize, GemmCfg<128>::SMEM);
    cudaFuncSetAttribute((tc_gemm<2, 128, 12>), cudaFuncAttributeMaxDynamicSharedMemorySize, GemmCfg<128>::SMEM);
    cudaFuncSetAttribute((tc_gemm<1, 64, 12>),  cudaFuncAttributeMaxDynamicSharedMemorySize, GemmCfg<64>::SMEM);
    cudaFuncSetAttribute((tc_gemm<1, 64, 48>),  cudaFuncAttributeMaxDynamicSharedMemorySize, GemmCfg<64>::SMEM);
    cudaFuncSetAttribute(attn_tc, cudaFuncAttributeMaxDynamicSharedMemorySize, ATTN_SMEM);

    // 0) weights -> fp16 [N,K], single launch
    wconv_all<<<WT_TOT, dim3(32, 8)>>>(W_qkv, W_attn, W_fc, W_mlp, wq, wa, wf, wm);

    // 1) LN1 -> fp16
    ln_kernel<<<BT_ / 8, 256>>>(x, ln1_g, ln1_b, ln);
    // 2) QKV = ln1 @ W_qkv -> fp16
    tc_gemm<0, 128, 12><<<dim3(3 * C_ / 128, BT_ / 128), 256, GemmCfg<128>::SMEM>>>(
        ln, wq, nullptr, qkv, BT_, 3 * C_);
    // 3) causal flash attention (fp16 mma, ldmatrix)
    attn_tc<<<dim3(T_ / 64, B_ * H_), 128, ATTN_SMEM>>>(qkv, yb);
    // 4) x1 = x + y @ W_attn_proj (fp32 out), BN=64
    tc_gemm<1, 64, 12><<<dim3(C_ / 64, BT_ / 128), 256, GemmCfg<64>::SMEM>>>(
        yb, wa, x, x1, BT_, C_);
    // 5) LN2 -> fp16
    ln_kernel<<<BT_ / 8, 256>>>(x1, ln2_g, ln2_b, ln);
    // 6) h = gelu(ln2 @ W_fc) -> fp16
    tc_gemm<2, 128, 12><<<dim3(4 * C_ / 128, BT_ / 128), 256, GemmCfg<128>::SMEM>>>(
        ln, wf, nullptr, hb, BT_, 4 * C_);
    // 7) out = x1 + h @ W_mlp_proj (fp32 out), BN=64
    tc_gemm<1, 64, 48><<<dim3(C_ / 64, BT_ / 128), 256, GemmCfg<64>::SMEM>>>(
        hb, wm, x1, out, BT_, C_);
}